// round 14
// baseline (speedup 1.0000x reference)
#include <cuda_runtime.h>
#include <cuda_fp16.h>
#include <cfloat>
#include <cstdint>

// Problem constants
#define B_   32
#define N_   512
#define D_   791
#define H_   7
#define DK_  113
#define M_   (B_ * N_)     // 16384
#define MAXP 64

// main HMMA GEMM: CTA 128x128, warp tile 32x64, 8 warps, 3-stage, 2 CTA/SM
#define KP_     832          // padded K (13 * 64)
#define NCH     13           // single hi term, 13 chunks of K=64
#define NPAD_   2432         // fused N = 3*791 = 2373 padded to 19*128
#define STAGE_B 32768        // A 128x64 fp16 (16KB) + B 128x64 fp16 (16KB)
#define GEMM_SMEM (3 * STAGE_B + 256)
#define BHN (B_ * H_ * N_)   // 114688 packed rows

// score GEMM: CTA 128x128, warp tile 32x64, K = 2 terms x 128 (4 chunks), 3-stage
#define SKP   128
#define SNCH  4
#define SSTAGE_B 32768
#define SGEMM_SMEM (3 * SSTAGE_B + 256)
#define EPI_STRIDE 272       // fp16 staging row stride (bytes): 16B-aligned, conflict-free

// ---------------- scratch (device globals; no allocation allowed) -------------
__device__ __align__(256) __half g_Ahi[M_ * KP_];
__device__ __align__(256) __half g_Bh [NPAD_ * KP_];   // zero-init; transB fills n<791
__device__ __align__(256) __half g_Qhi[(size_t)BHN * SKP];
__device__ __align__(256) __half g_Qlo[(size_t)BHN * SKP];
__device__ __align__(256) __half g_Khi[(size_t)BHN * SKP];
__device__ __align__(256) __half g_S[(size_t)B_ * H_ * N_ * N_];
__device__ float g_q[M_ * D_];
__device__ float g_k[M_ * D_];
__device__ float g_h[M_ * D_];
__device__ float g_attn[B_ * N_ * N_];
__device__ int   g_pos[B_ * MAXP * 2];
__device__ int   g_cnt[B_];

// ---------------- PTX helpers --------------------------------------------------
__device__ __forceinline__ uint32_t smem_u32(const void* p) {
    uint32_t a;
    asm("{ .reg .u64 t; cvta.to.shared.u64 t, %1; cvt.u32.u64 %0, t; }" : "=r"(a) : "l"(p));
    return a;
}
__device__ __forceinline__ void ldm4(uint32_t& r0, uint32_t& r1, uint32_t& r2,
                                     uint32_t& r3, uint32_t a) {
    asm volatile("ldmatrix.sync.aligned.m8n8.x4.shared.b16 {%0,%1,%2,%3}, [%4];"
                 : "=r"(r0), "=r"(r1), "=r"(r2), "=r"(r3) : "r"(a));
}
__device__ __forceinline__ void mma16816(float* d, const uint32_t* a, const uint32_t* b) {
    asm volatile(
        "mma.sync.aligned.m16n8k16.row.col.f32.f16.f16.f32 "
        "{%0,%1,%2,%3}, {%4,%5,%6,%7}, {%8,%9}, {%0,%1,%2,%3};"
        : "+f"(d[0]), "+f"(d[1]), "+f"(d[2]), "+f"(d[3])
        : "r"(a[0]), "r"(a[1]), "r"(a[2]), "r"(a[3]), "r"(b[0]), "r"(b[1]));
}
__device__ __forceinline__ void cpa16(uint32_t dst, const void* src) {
    asm volatile("cp.async.cg.shared.global [%0], [%1], 16;" :: "r"(dst), "l"(src));
}

// ---------------- conversions ----------------------------------------------------
__global__ __launch_bounds__(256) void convA_kernel(
    const float* __restrict__ fuse, __half* __restrict__ Ahi)
{
    int idx = blockIdx.x * 256 + threadIdx.x;      // over M_*KP_/4
    if (idx >= M_ * KP_ / 4) return;
    int m = idx / (KP_ / 4);
    int k = (idx - m * (KP_ / 4)) * 4;
    const float* src = fuse + (size_t)m * D_ + k;
    float x0 = (k     < D_) ? __ldg(src)     : 0.f;
    float x1 = (k + 1 < D_) ? __ldg(src + 1) : 0.f;
    float x2 = (k + 2 < D_) ? __ldg(src + 2) : 0.f;
    float x3 = (k + 3 < D_) ? __ldg(src + 3) : 0.f;
    __half2 h01 = __floats2half2_rn(x0, x1);
    __half2 h23 = __floats2half2_rn(x2, x3);
    uint2 o;
    o.x = *reinterpret_cast<uint32_t*>(&h01);
    o.y = *reinterpret_cast<uint32_t*>(&h23);
    *reinterpret_cast<uint2*>(Ahi + (size_t)idx * 4) = o;
}

// Coalesced transpose: Bh[z*791 + n][k] = W_z[k][n], 32x32 smem tiles.
// Rows n >= 3*791 stay zero (static zero-init; never written, outputs discarded).
__global__ __launch_bounds__(256) void transB_kernel(
    const float* __restrict__ Wq, const float* __restrict__ Wk,
    const float* __restrict__ Wgc, __half* __restrict__ Bh)
{
    __shared__ __half tile[32][33];
    const int z = blockIdx.z;
    const float* W = (z == 0) ? Wq : (z == 1) ? Wk : Wgc;
    const int k0 = blockIdx.x * 32;
    const int n0 = blockIdx.y * 32;
    const int tx = threadIdx.x & 31, ty = threadIdx.x >> 5;

    #pragma unroll
    for (int rr = 0; rr < 4; rr++) {
        int k = k0 + ty + rr * 8;
        int n = n0 + tx;
        float v = (k < D_ && n < D_) ? W[(size_t)k * D_ + n] : 0.f;
        tile[ty + rr * 8][tx] = __float2half_rn(v);
    }
    __syncthreads();
    #pragma unroll
    for (int rr = 0; rr < 4; rr++) {
        int n = n0 + ty + rr * 8;
        int k = k0 + tx;
        if (n < D_ && k < KP_)
            Bh[(size_t)(z * D_ + n) * KP_ + k] = tile[tx][ty + rr * 8];
    }
}

// ---------------- HMMA fused GEMM (single hi term, 128x128, 3-stage) -------------
__device__ __forceinline__ void issue_chunk(
    int cc, int tid, int m0, int nt0, uint32_t sb,
    const __half* __restrict__ Ahi, const __half* __restrict__ Bh)
{
    const int kk0 = cc * 64;
    const uint32_t st = sb + (cc % 3) * STAGE_B;
    #pragma unroll
    for (int it = 0; it < 4; it++) {               // A: 1024 x 16B
        int i = tid + it * 256;
        int r = i >> 3, u = i & 7;
        const __half* src = Ahi + (size_t)(m0 + r) * KP_ + kk0 + u * 8;
        cpa16(st + r * 128 + (((u ^ (r & 7))) << 4), src);
    }
    #pragma unroll
    for (int it = 0; it < 4; it++) {               // B: 1024 x 16B
        int i = tid + it * 256;
        int r = i >> 3, u = i & 7;
        const __half* src = Bh + (size_t)(nt0 + r) * KP_ + kk0 + u * 8;
        cpa16(st + 16384 + r * 128 + (((u ^ (r & 7))) << 4), src);
    }
    asm volatile("cp.async.commit_group;" ::: "memory");
}

__global__ __launch_bounds__(256, 2) void gemm_hmma_kernel(
    const __half* __restrict__ Ahi, const __half* __restrict__ Bh,
    const float* __restrict__ bq, const float* __restrict__ bk,
    float* __restrict__ q, float* __restrict__ kk, float* __restrict__ hid)
{
    extern __shared__ char smc[];
    const uint32_t sb = (smem_u32(smc) + 127) & ~127u;
    const int tid = threadIdx.x;
    const int wid = tid >> 5, lane = tid & 31;
    const int m0 = blockIdx.y * 128;
    const int nt0 = blockIdx.x * 128;

    float acc[2][8][4];
    #pragma unroll
    for (int t = 0; t < 2; t++)
        #pragma unroll
        for (int j = 0; j < 8; j++)
            #pragma unroll
            for (int e = 0; e < 4; e++) acc[t][j][e] = 0.f;

    issue_chunk(0, tid, m0, nt0, sb, Ahi, Bh);
    issue_chunk(1, tid, m0, nt0, sb, Ahi, Bh);

    const int warp_m = wid & 3, warp_n = wid >> 2;
    const int rowinA = (lane & 7) + ((lane >> 3) & 1) * 8;
    const int hbA    = lane >> 4;
    const int rowinB = (lane & 7) + ((lane >> 4) & 1) * 8;
    const int hbB    = (lane >> 3) & 1;

    for (int cc = 0; cc < NCH; cc++) {
        if (cc == NCH - 1) asm volatile("cp.async.wait_group 0;" ::: "memory");
        else               asm volatile("cp.async.wait_group 1;" ::: "memory");
        __syncthreads();
        if (cc + 2 < NCH) issue_chunk(cc + 2, tid, m0, nt0, sb, Ahi, Bh);

        const uint32_t st = sb + (cc % 3) * STAGE_B;
        #pragma unroll
        for (int s = 0; s < 4; s++) {
            uint32_t a[2][4], b[8][2];
            #pragma unroll
            for (int t = 0; t < 2; t++) {
                int r = warp_m * 32 + t * 16 + rowinA;
                uint32_t ad = st + r * 128 + ((((s << 1) | hbA) ^ (r & 7)) << 4);
                ldm4(a[t][0], a[t][1], a[t][2], a[t][3], ad);
            }
            #pragma unroll
            for (int jj = 0; jj < 4; jj++) {
                int r = warp_n * 64 + jj * 16 + rowinB;
                uint32_t ad = st + 16384 + r * 128 + ((((s << 1) | hbB) ^ (r & 7)) << 4);
                ldm4(b[2 * jj][0], b[2 * jj][1], b[2 * jj + 1][0], b[2 * jj + 1][1], ad);
            }
            #pragma unroll
            for (int t = 0; t < 2; t++)
                #pragma unroll
                for (int j = 0; j < 8; j++)
                    mma16816(acc[t][j], a[t], b[j]);
        }
    }

    // epilogue: demux to q | k | hid with bias (contiguous fp32 stores)
    #pragma unroll
    for (int t = 0; t < 2; t++) {
        const int row0 = m0 + warp_m * 32 + t * 16 + (lane >> 2);
        #pragma unroll
        for (int j = 0; j < 8; j++) {
            const int col = nt0 + warp_n * 64 + j * 8 + (lane & 3) * 2;
            #pragma unroll
            for (int half = 0; half < 2; half++) {
                const int row = row0 + half * 8;
                const float v0 = acc[t][j][half * 2];
                const float v1 = acc[t][j][half * 2 + 1];
                #pragma unroll
                for (int e = 0; e < 2; e++) {
                    const int c = col + e;
                    const float v = e ? v1 : v0;
                    if (c < D_)
                        q[(size_t)row * D_ + c] = v + __ldg(&bq[c]);
                    else if (c < 2 * D_)
                        kk[(size_t)row * D_ + (c - D_)] = v + __ldg(&bk[c - D_]);
                    else if (c < 3 * D_)
                        hid[(size_t)row * D_ + (c - 2 * D_)] = v;
                }
            }
        }
    }
}

// ---------------- pack q/k: q -> hi/lo, k -> hi only (8 elems/thread) -----------
__global__ __launch_bounds__(256) void pack_qk_kernel(
    const float* __restrict__ q, const float* __restrict__ k,
    __half* __restrict__ Qhi, __half* __restrict__ Qlo, __half* __restrict__ Khi)
{
    int idx = blockIdx.x * 256 + threadIdx.x;      // over BHN*16 (8 elems each)
    if (idx >= BHN * 16) return;
    const int dk0 = (idx & 15) * 8;
    const int rest = idx >> 4;
    const int n = rest & (N_ - 1);
    const int bh = rest >> 9;
    const int h = bh % H_, b = bh / H_;
    const size_t off = ((size_t)(b * N_ + n)) * D_ + h * DK_;

    uint32_t qh[4], ql[4], kh[4];
    #pragma unroll
    for (int p = 0; p < 4; p++) {
        float qv0 = 0.f, qv1 = 0.f, kv0 = 0.f, kv1 = 0.f;
        int d0 = dk0 + p * 2, d1 = d0 + 1;
        if (d0 < DK_) { qv0 = __ldg(&q[off + d0]); kv0 = __ldg(&k[off + d0]); }
        if (d1 < DK_) { qv1 = __ldg(&q[off + d1]); kv1 = __ldg(&k[off + d1]); }
        __half2 qh2 = __floats2half2_rn(qv0, qv1);
        __half2 kh2 = __floats2half2_rn(kv0, kv1);
        __half2 ql2 = __floats2half2_rn(qv0 - __half2float(__low2half(qh2)),
                                        qv1 - __half2float(__high2half(qh2)));
        qh[p] = *reinterpret_cast<uint32_t*>(&qh2);
        ql[p] = *reinterpret_cast<uint32_t*>(&ql2);
        kh[p] = *reinterpret_cast<uint32_t*>(&kh2);
    }
    const size_t dst = (size_t)idx * 8;
    *reinterpret_cast<uint4*>(Qhi + dst) = make_uint4(qh[0], qh[1], qh[2], qh[3]);
    *reinterpret_cast<uint4*>(Qlo + dst) = make_uint4(ql[0], ql[1], ql[2], ql[3]);
    *reinterpret_cast<uint4*>(Khi + dst) = make_uint4(kh[0], kh[1], kh[2], kh[3]);
}

// ---------------- HMMA score GEMM (2 terms, 3-stage, fp16 output) ----------------
// S[bh] = (Qhi + Qlo) @ Khi^T, scaled by 1/sqrt(113), stored fp16 via smem staging.
__device__ __forceinline__ void issue_chunk_s(
    int cc, int tid, int m0, int nt0, int bh, uint32_t sb,
    const __half* __restrict__ Qhi, const __half* __restrict__ Qlo,
    const __half* __restrict__ Khi)
{
    const int kk0 = (cc & 1) * 64;
    const __half* As = (cc >= 2) ? Qlo : Qhi;
    const size_t base = (size_t)bh * N_ * SKP;
    const uint32_t st = sb + (cc % 3) * SSTAGE_B;
    #pragma unroll
    for (int it = 0; it < 4; it++) {               // A: 1024 x 16B
        int i = tid + it * 256;
        int r = i >> 3, u = i & 7;
        const __half* src = As + base + (size_t)(m0 + r) * SKP + kk0 + u * 8;
        cpa16(st + r * 128 + (((u ^ (r & 7))) << 4), src);
    }
    #pragma unroll
    for (int it = 0; it < 4; it++) {               // B: 1024 x 16B
        int i = tid + it * 256;
        int r = i >> 3, u = i & 7;
        const __half* src = Khi + base + (size_t)(nt0 + r) * SKP + kk0 + u * 8;
        cpa16(st + 16384 + r * 128 + (((u ^ (r & 7))) << 4), src);
    }
    asm volatile("cp.async.commit_group;" ::: "memory");
}

__global__ __launch_bounds__(256, 2) void score_hmma_kernel(
    const __half* __restrict__ Qhi, const __half* __restrict__ Qlo,
    const __half* __restrict__ Khi, __half* __restrict__ S)
{
    extern __shared__ char smc[];
    char* smb = (char*)(((uintptr_t)smc + 127) & ~(uintptr_t)127);
    const uint32_t sb = smem_u32(smb);
    const int tid = threadIdx.x;
    const int wid = tid >> 5, lane = tid & 31;
    const int m0 = blockIdx.y * 128;
    const int nt0 = blockIdx.x * 128;
    const int bh = blockIdx.z;

    float acc[2][8][4];
    #pragma unroll
    for (int t = 0; t < 2; t++)
        #pragma unroll
        for (int j = 0; j < 8; j++)
            #pragma unroll
            for (int e = 0; e < 4; e++) acc[t][j][e] = 0.f;

    issue_chunk_s(0, tid, m0, nt0, bh, sb, Qhi, Qlo, Khi);
    issue_chunk_s(1, tid, m0, nt0, bh, sb, Qhi, Qlo, Khi);

    const int warp_m = wid & 3, warp_n = wid >> 2;
    const int rowinA = (lane & 7) + ((lane >> 3) & 1) * 8;
    const int hbA    = lane >> 4;
    const int rowinB = (lane & 7) + ((lane >> 4) & 1) * 8;
    const int hbB    = (lane >> 3) & 1;

    for (int cc = 0; cc < SNCH; cc++) {
        if (cc == SNCH - 1) asm volatile("cp.async.wait_group 0;" ::: "memory");
        else                asm volatile("cp.async.wait_group 1;" ::: "memory");
        __syncthreads();
        if (cc + 2 < SNCH) issue_chunk_s(cc + 2, tid, m0, nt0, bh, sb, Qhi, Qlo, Khi);

        const uint32_t st = sb + (cc % 3) * SSTAGE_B;
        #pragma unroll
        for (int s = 0; s < 4; s++) {
            uint32_t a[2][4], b[8][2];
            #pragma unroll
            for (int t = 0; t < 2; t++) {
                int r = warp_m * 32 + t * 16 + rowinA;
                uint32_t ad = st + r * 128 + ((((s << 1) | hbA) ^ (r & 7)) << 4);
                ldm4(a[t][0], a[t][1], a[t][2], a[t][3], ad);
            }
            #pragma unroll
            for (int jj = 0; jj < 4; jj++) {
                int r = warp_n * 64 + jj * 16 + rowinB;
                uint32_t ad = st + 16384 + r * 128 + ((((s << 1) | hbB) ^ (r & 7)) << 4);
                ldm4(b[2 * jj][0], b[2 * jj][1], b[2 * jj + 1][0], b[2 * jj + 1][1], ad);
            }
            #pragma unroll
            for (int t = 0; t < 2; t++)
                #pragma unroll
                for (int j = 0; j < 8; j++)
                    mma16816(acc[t][j], a[t], b[j]);
        }
    }

    // ---- fp16 epilogue: stage 128x128 half tile in smem, write coalesced ----
    __syncthreads();                       // all warps done reading stage buffers
    const float scale = rsqrtf((float)DK_);
    #pragma unroll
    for (int t = 0; t < 2; t++) {
        const int rl0 = warp_m * 32 + t * 16 + (lane >> 2);
        #pragma unroll
        for (int j = 0; j < 8; j++) {
            const int cl = warp_n * 64 + j * 8 + (lane & 3) * 2;
            #pragma unroll
            for (int half = 0; half < 2; half++) {
                const int rl = rl0 + half * 8;
                __half2 hv = __floats2half2_rn(acc[t][j][half * 2] * scale,
                                               acc[t][j][half * 2 + 1] * scale);
                *reinterpret_cast<uint32_t*>(smb + rl * EPI_STRIDE + cl * 2) =
                    *reinterpret_cast<uint32_t*>(&hv);
            }
        }
    }
    __syncthreads();

    // 256 threads x (1 row-half of 128B each): fully coalesced fp16 stores
    {
        const int row = tid >> 1, seg = tid & 1;
        const char* src = smb + row * EPI_STRIDE + seg * 128;
        __half* dst = S + (size_t)bh * N_ * N_ + (size_t)(m0 + row) * N_ + nt0 + seg * 64;
        #pragma unroll
        for (int u = 0; u < 8; u++)
            *reinterpret_cast<uint4*>(dst + u * 8) =
                *reinterpret_cast<const uint4*>(src + u * 16);
    }
}

// ---------------- softmax + head-sum -> attn (fp16 S input) ----------------------
__global__ __launch_bounds__(256) void softmax_kernel(
    const __half* __restrict__ S, float* __restrict__ attn)
{
    __shared__ float e[H_][N_];
    __shared__ float winv[H_];

    const int tid = threadIdx.x;
    const int wid = tid >> 5, lane = tid & 31;
    const int ng = blockIdx.x;
    const int b = ng >> 9, n = ng & (N_ - 1);

    if (wid < H_) {
        const __half2* Sr2 = reinterpret_cast<const __half2*>(
            S + ((size_t)(b * H_ + wid) * N_ + n) * N_);
        float v[16];
        float mx = -FLT_MAX;
        #pragma unroll
        for (int it = 0; it < 8; it++) {
            float2 f = __half22float2(Sr2[lane + it * 32]);
            v[2 * it] = f.x;
            v[2 * it + 1] = f.y;
            mx = fmaxf(mx, fmaxf(f.x, f.y));
        }
        #pragma unroll
        for (int o = 16; o > 0; o >>= 1) mx = fmaxf(mx, __shfl_xor_sync(0xFFFFFFFFu, mx, o));
        float sum = 0.f;
        #pragma unroll
        for (int it = 0; it < 8; it++) {
            float e0 = __expf(v[2 * it] - mx);
            float e1 = __expf(v[2 * it + 1] - mx);
            e[wid][(lane + it * 32) * 2]     = e0;
            e[wid][(lane + it * 32) * 2 + 1] = e1;
            sum += e0 + e1;
        }
        #pragma unroll
        for (int o = 16; o > 0; o >>= 1) sum += __shfl_xor_sync(0xFFFFFFFFu, sum, o);
        if (lane == 0) winv[wid] = __frcp_rn(sum);
    }
    __syncthreads();

    float* an = attn + (size_t)ng * N_;
    for (int m = tid; m < N_; m += 256) {
        float a = 0.f;
        #pragma unroll
        for (int h = 0; h < H_; h++) a += e[h][m] * winv[h];
        an[m] = a;
    }
}

// ---------------- per-batch top-2 threshold + positions -------------------------
__global__ __launch_bounds__(256) void top2_kernel(
    const float* __restrict__ attn, int* __restrict__ pos, int* __restrict__ cnt)
{
    __shared__ float v1s[256], v2s[256];
    __shared__ float s_kth;
    __shared__ int   s_cnt;

    const int b = blockIdx.x;
    const int tid = threadIdx.x;
    const float* A = attn + (size_t)b * N_ * N_;

    float v1 = -FLT_MAX, v2 = -FLT_MAX;
    for (int i = tid; i < N_ * N_; i += 256) {
        float v = A[i];
        if (v > v1) { v2 = v1; v1 = v; }
        else if (v > v2) v2 = v;
    }
    v1s[tid] = v1; v2s[tid] = v2;
    __syncthreads();
    if (tid == 0) {
        float t1 = -FLT_MAX, t2 = -FLT_MAX;
        for (int i = 0; i < 256; i++) {
            float a = v1s[i], c = v2s[i];
            if (a > t1) { t2 = t1; t1 = a; } else if (a > t2) t2 = a;
            if (c > t1) { t2 = t1; t1 = c; } else if (c > t2) t2 = c;
        }
        s_kth = t2;
        s_cnt = 0;
    }
    __syncthreads();
    const float kth = s_kth;
    const int base = b * MAXP * 2;
    for (int i = tid; i < N_ * N_; i += 256) {
        if (A[i] >= kth) {
            int idx = atomicAdd(&s_cnt, 1);
            if (idx < MAXP) {
                pos[base + idx * 2]     = i >> 9;
                pos[base + idx * 2 + 1] = i & (N_ - 1);
            }
        }
    }
    __syncthreads();
    if (tid == 0) {
        int c = s_cnt < MAXP ? s_cnt : MAXP;
        for (int a2 = 1; a2 < c; a2++) {
            int ki = pos[base + a2 * 2], kj = pos[base + a2 * 2 + 1];
            int key = ki * N_ + kj;
            int p = a2 - 1;
            while (p >= 0) {
                int pi = pos[base + p * 2], pj = pos[base + p * 2 + 1];
                if (pi * N_ + pj <= key) break;
                pos[base + (p + 1) * 2] = pi;
                pos[base + (p + 1) * 2 + 1] = pj;
                p--;
            }
            pos[base + (p + 1) * 2] = ki;
            pos[base + (p + 1) * 2 + 1] = kj;
        }
        cnt[b] = c;
    }
}

// ---------------- sparse adjacency apply + GC epilogue --------------------------
__global__ __launch_bounds__(256) void out_kernel(
    const float* __restrict__ attn, const float* __restrict__ hidden,
    const float* __restrict__ bgc, const int* __restrict__ pos,
    const int* __restrict__ cnt, float* __restrict__ out)
{
    const int b = blockIdx.y;
    const int n = blockIdx.x;
    const int tid = threadIdx.x;

    __shared__ int   s_nc;
    __shared__ int   s_cols[2 * MAXP];
    __shared__ float s_w[2 * MAXP];
    __shared__ float s_wd, s_inv;

    if (tid == 0) {
        const float* An = attn + ((size_t)b * N_ + n) * N_;
        const int base = b * MAXP * 2;
        int c = cnt[b];
        int nc = 0;
        float wd = An[n];
        float sum = wd;
        for (int e = 0; e < c; e++) {
            int i = pos[base + e * 2], j = pos[base + e * 2 + 1];
            if (i == n && j != n) { float w = An[j]; s_cols[nc] = j; s_w[nc] = w; sum += w; nc++; }
            if (j == n && i != n) { float w = An[i]; s_cols[nc] = i; s_w[nc] = w; sum += w; nc++; }
        }
        s_nc = nc; s_wd = wd; s_inv = 1.f / (sum + 1.f);
    }
    __syncthreads();

    const int nc = s_nc;
    const float wd = s_wd, inv = s_inv;
    const float* hn = hidden + ((size_t)b * N_ + n) * D_;
    float* on = out + ((size_t)b * N_ + n) * D_;

    for (int d = tid; d < D_; d += 256) {
        float v = wd * hn[d];
        for (int e = 0; e < nc; e++)
            v += s_w[e] * hidden[((size_t)b * N_ + s_cols[e]) * D_ + d];
        v = v * inv + __ldg(&bgc[d]);
        on[d] = fmaxf(v, 0.f);
    }
}

// ---------------- launch ------------------------------------------------------
extern "C" void kernel_launch(void* const* d_in, const int* in_sizes, int n_in,
                              void* d_out, int out_size)
{
    const float* fuse = (const float*)d_in[0];
    const float* Wq   = (const float*)d_in[1];
    const float* bq   = (const float*)d_in[2];
    const float* Wk   = (const float*)d_in[3];
    const float* bk   = (const float*)d_in[4];
    const float* Wgc  = (const float*)d_in[5];
    const float* bgc  = (const float*)d_in[6];
    float* out = (float*)d_out;

    __half *Ahi, *Bh, *Qhi, *Qlo, *Khi, *S;
    float *q, *k, *hid, *attn;
    int *pos, *cnt;
    cudaGetSymbolAddress((void**)&Ahi,  g_Ahi);
    cudaGetSymbolAddress((void**)&Bh,   g_Bh);
    cudaGetSymbolAddress((void**)&Qhi,  g_Qhi);
    cudaGetSymbolAddress((void**)&Qlo,  g_Qlo);
    cudaGetSymbolAddress((void**)&Khi,  g_Khi);
    cudaGetSymbolAddress((void**)&S,    g_S);
    cudaGetSymbolAddress((void**)&q,    g_q);
    cudaGetSymbolAddress((void**)&k,    g_k);
    cudaGetSymbolAddress((void**)&hid,  g_h);
    cudaGetSymbolAddress((void**)&attn, g_attn);
    cudaGetSymbolAddress((void**)&pos,  g_pos);
    cudaGetSymbolAddress((void**)&cnt,  g_cnt);

    // 0) fp16 conversions: A hi-only (vectorized); B via coalesced transpose
    //    (Bh padding rows stay zero from static init; never modified)
    convA_kernel<<<(M_ * KP_ / 4 + 255) / 256, 256>>>(fuse, Ahi);
    transB_kernel<<<dim3(KP_ / 32, (D_ + 31) / 32, 3), 256>>>(Wq, Wk, Wgc, Bh);

    // 1) fused HMMA GEMM (hi term only, 2 CTA/SM) -> q, k, hidden
    cudaFuncSetAttribute(gemm_hmma_kernel, cudaFuncAttributeMaxDynamicSharedMemorySize, GEMM_SMEM);
    gemm_hmma_kernel<<<dim3(NPAD_ / 128, M_ / 128), 256, GEMM_SMEM>>>(
        Ahi, Bh, bq, bk, q, k, hid);

    // 2) pack q (hi/lo) and k (hi) head-padded fp16 (vectorized)
    pack_qk_kernel<<<(BHN * 16 + 255) / 256, 256>>>(q, k, Qhi, Qlo, Khi);

    // 3) HMMA score GEMM (2 terms, 2 CTA/SM) -> S[B,H,N,N] fp16
    cudaFuncSetAttribute(score_hmma_kernel, cudaFuncAttributeMaxDynamicSharedMemorySize, SGEMM_SMEM);
    score_hmma_kernel<<<dim3(N_ / 128, N_ / 128, B_ * H_), 256, SGEMM_SMEM>>>(
        Qhi, Qlo, Khi, S);

    // 4) softmax + head-sum -> attn
    softmax_kernel<<<M_, 256>>>(S, attn);

    // 5) per-batch top-2 threshold + sparse positions
    top2_kernel<<<B_, 256>>>(attn, pos, cnt);

    // 6) sparse adjacency apply + graph-conv epilogue
    out_kernel<<<dim3(N_, B_), 256>>>(attn, hid, bgc, pos, cnt, out);
}

// round 15
// speedup vs baseline: 1.0652x; 1.0652x over previous
#include <cuda_runtime.h>
#include <cuda_fp16.h>
#include <cfloat>
#include <cstdint>

// Problem constants
#define B_   32
#define N_   512
#define D_   791
#define H_   7
#define DK_  113
#define M_   (B_ * N_)     // 16384
#define MAXP 64
#define QP_  792            // padded row stride for q/k/hid (fp32), 8B-aligned pairs

// main HMMA GEMM: CTA 128x128, warp tile 32x64, 8 warps, 3-stage, 2 CTA/SM
#define KP_     832          // padded K (13 * 64)
#define NCH     13           // single hi term, 13 chunks of K=64
#define NPAD_   2432         // fused N = 3*791 = 2373 padded to 19*128
#define STAGE_B 32768        // A 128x64 fp16 (16KB) + B 128x64 fp16 (16KB)
#define GEMM_SMEM (3 * STAGE_B + 256)
#define BHN (B_ * H_ * N_)   // 114688 packed rows

// score GEMM: CTA 128x128, 2 k-half stages of {Qhi,Qlo,Khi} (48KB each)
#define SKP   128
#define SSTAGE_B 49152
#define SGEMM_SMEM (2 * SSTAGE_B + 256)
#define EPI_STRIDE 272       // fp16 staging row stride (bytes): 16B-aligned, conflict-free

// ---------------- scratch (device globals; no allocation allowed) -------------
__device__ __align__(256) __half g_Ahi[M_ * KP_];
__device__ __align__(256) __half g_Bh [NPAD_ * KP_];   // zero-init; transB fills n<791
__device__ __align__(256) __half g_Qhi[(size_t)BHN * SKP];
__device__ __align__(256) __half g_Qlo[(size_t)BHN * SKP];
__device__ __align__(256) __half g_Khi[(size_t)BHN * SKP];
__device__ __align__(256) __half g_S[(size_t)B_ * H_ * N_ * N_];
__device__ __align__(256) float g_q[(size_t)M_ * QP_];
__device__ __align__(256) float g_k[(size_t)M_ * QP_];
__device__ __align__(256) float g_h[(size_t)M_ * QP_];
__device__ float g_attn[B_ * N_ * N_];
__device__ int   g_pos[B_ * MAXP * 2];
__device__ int   g_cnt[B_];

// ---------------- PTX helpers --------------------------------------------------
__device__ __forceinline__ uint32_t smem_u32(const void* p) {
    uint32_t a;
    asm("{ .reg .u64 t; cvta.to.shared.u64 t, %1; cvt.u32.u64 %0, t; }" : "=r"(a) : "l"(p));
    return a;
}
__device__ __forceinline__ void ldm4(uint32_t& r0, uint32_t& r1, uint32_t& r2,
                                     uint32_t& r3, uint32_t a) {
    asm volatile("ldmatrix.sync.aligned.m8n8.x4.shared.b16 {%0,%1,%2,%3}, [%4];"
                 : "=r"(r0), "=r"(r1), "=r"(r2), "=r"(r3) : "r"(a));
}
__device__ __forceinline__ void mma16816(float* d, const uint32_t* a, const uint32_t* b) {
    asm volatile(
        "mma.sync.aligned.m16n8k16.row.col.f32.f16.f16.f32 "
        "{%0,%1,%2,%3}, {%4,%5,%6,%7}, {%8,%9}, {%0,%1,%2,%3};"
        : "+f"(d[0]), "+f"(d[1]), "+f"(d[2]), "+f"(d[3])
        : "r"(a[0]), "r"(a[1]), "r"(a[2]), "r"(a[3]), "r"(b[0]), "r"(b[1]));
}
__device__ __forceinline__ void cpa16(uint32_t dst, const void* src) {
    asm volatile("cp.async.cg.shared.global [%0], [%1], 16;" :: "r"(dst), "l"(src));
}

// ---------------- conversions ----------------------------------------------------
__global__ __launch_bounds__(256) void convA_kernel(
    const float* __restrict__ fuse, __half* __restrict__ Ahi)
{
    int idx = blockIdx.x * 256 + threadIdx.x;      // over M_*KP_/4
    if (idx >= M_ * KP_ / 4) return;
    int m = idx / (KP_ / 4);
    int k = (idx - m * (KP_ / 4)) * 4;
    const float* src = fuse + (size_t)m * D_ + k;
    float x0 = (k     < D_) ? __ldg(src)     : 0.f;
    float x1 = (k + 1 < D_) ? __ldg(src + 1) : 0.f;
    float x2 = (k + 2 < D_) ? __ldg(src + 2) : 0.f;
    float x3 = (k + 3 < D_) ? __ldg(src + 3) : 0.f;
    __half2 h01 = __floats2half2_rn(x0, x1);
    __half2 h23 = __floats2half2_rn(x2, x3);
    uint2 o;
    o.x = *reinterpret_cast<uint32_t*>(&h01);
    o.y = *reinterpret_cast<uint32_t*>(&h23);
    *reinterpret_cast<uint2*>(Ahi + (size_t)idx * 4) = o;
}

// Coalesced transpose: Bh[z*791 + n][k] = W_z[k][n], 32x32 smem tiles.
__global__ __launch_bounds__(256) void transB_kernel(
    const float* __restrict__ Wq, const float* __restrict__ Wk,
    const float* __restrict__ Wgc, __half* __restrict__ Bh)
{
    __shared__ __half tile[32][33];
    const int z = blockIdx.z;
    const float* W = (z == 0) ? Wq : (z == 1) ? Wk : Wgc;
    const int k0 = blockIdx.x * 32;
    const int n0 = blockIdx.y * 32;
    const int tx = threadIdx.x & 31, ty = threadIdx.x >> 5;

    #pragma unroll
    for (int rr = 0; rr < 4; rr++) {
        int k = k0 + ty + rr * 8;
        int n = n0 + tx;
        float v = (k < D_ && n < D_) ? W[(size_t)k * D_ + n] : 0.f;
        tile[ty + rr * 8][tx] = __float2half_rn(v);
    }
    __syncthreads();
    #pragma unroll
    for (int rr = 0; rr < 4; rr++) {
        int n = n0 + ty + rr * 8;
        int k = k0 + tx;
        if (n < D_ && k < KP_)
            Bh[(size_t)(z * D_ + n) * KP_ + k] = tile[tx][ty + rr * 8];
    }
}

// ---------------- HMMA fused GEMM (single hi term, 128x128, 3-stage) -------------
__device__ __forceinline__ void issue_chunk(
    int cc, int tid, int m0, int nt0, uint32_t sb,
    const __half* __restrict__ Ahi, const __half* __restrict__ Bh)
{
    const int kk0 = cc * 64;
    const uint32_t st = sb + (cc % 3) * STAGE_B;
    #pragma unroll
    for (int it = 0; it < 4; it++) {               // A: 1024 x 16B
        int i = tid + it * 256;
        int r = i >> 3, u = i & 7;
        const __half* src = Ahi + (size_t)(m0 + r) * KP_ + kk0 + u * 8;
        cpa16(st + r * 128 + (((u ^ (r & 7))) << 4), src);
    }
    #pragma unroll
    for (int it = 0; it < 4; it++) {               // B: 1024 x 16B
        int i = tid + it * 256;
        int r = i >> 3, u = i & 7;
        const __half* src = Bh + (size_t)(nt0 + r) * KP_ + kk0 + u * 8;
        cpa16(st + 16384 + r * 128 + (((u ^ (r & 7))) << 4), src);
    }
    asm volatile("cp.async.commit_group;" ::: "memory");
}

__global__ __launch_bounds__(256, 2) void gemm_hmma_kernel(
    const __half* __restrict__ Ahi, const __half* __restrict__ Bh,
    const float* __restrict__ bq, const float* __restrict__ bk,
    float* __restrict__ q, float* __restrict__ kk, float* __restrict__ hid)
{
    extern __shared__ char smc[];
    const uint32_t sb = (smem_u32(smc) + 127) & ~127u;
    const int tid = threadIdx.x;
    const int wid = tid >> 5, lane = tid & 31;
    const int m0 = blockIdx.y * 128;
    const int nt0 = blockIdx.x * 128;

    float acc[2][8][4];
    #pragma unroll
    for (int t = 0; t < 2; t++)
        #pragma unroll
        for (int j = 0; j < 8; j++)
            #pragma unroll
            for (int e = 0; e < 4; e++) acc[t][j][e] = 0.f;

    issue_chunk(0, tid, m0, nt0, sb, Ahi, Bh);
    issue_chunk(1, tid, m0, nt0, sb, Ahi, Bh);

    const int warp_m = wid & 3, warp_n = wid >> 2;
    const int rowinA = (lane & 7) + ((lane >> 3) & 1) * 8;
    const int hbA    = lane >> 4;
    const int rowinB = (lane & 7) + ((lane >> 4) & 1) * 8;
    const int hbB    = (lane >> 3) & 1;

    for (int cc = 0; cc < NCH; cc++) {
        if (cc == NCH - 1) asm volatile("cp.async.wait_group 0;" ::: "memory");
        else               asm volatile("cp.async.wait_group 1;" ::: "memory");
        __syncthreads();
        if (cc + 2 < NCH) issue_chunk(cc + 2, tid, m0, nt0, sb, Ahi, Bh);

        const uint32_t st = sb + (cc % 3) * STAGE_B;
        #pragma unroll
        for (int s = 0; s < 4; s++) {
            uint32_t a[2][4], b[8][2];
            #pragma unroll
            for (int t = 0; t < 2; t++) {
                int r = warp_m * 32 + t * 16 + rowinA;
                uint32_t ad = st + r * 128 + ((((s << 1) | hbA) ^ (r & 7)) << 4);
                ldm4(a[t][0], a[t][1], a[t][2], a[t][3], ad);
            }
            #pragma unroll
            for (int jj = 0; jj < 4; jj++) {
                int r = warp_n * 64 + jj * 16 + rowinB;
                uint32_t ad = st + 16384 + r * 128 + ((((s << 1) | hbB) ^ (r & 7)) << 4);
                ldm4(b[2 * jj][0], b[2 * jj][1], b[2 * jj + 1][0], b[2 * jj + 1][1], ad);
            }
            #pragma unroll
            for (int t = 0; t < 2; t++)
                #pragma unroll
                for (int j = 0; j < 8; j++)
                    mma16816(acc[t][j], a[t], b[j]);
        }
    }

    // epilogue: demux to q | k | hid with bias. Row stride QP_=792; k at +1 base.
    // col is always even, so fast-path pairs are 8B-aligned in every segment.
    #pragma unroll
    for (int t = 0; t < 2; t++) {
        const int row0 = m0 + warp_m * 32 + t * 16 + (lane >> 2);
        #pragma unroll
        for (int j = 0; j < 8; j++) {
            const int col = nt0 + warp_n * 64 + j * 8 + (lane & 3) * 2;
            #pragma unroll
            for (int half = 0; half < 2; half++) {
                const int row = row0 + half * 8;
                const float v0 = acc[t][j][half * 2];
                const float v1 = acc[t][j][half * 2 + 1];
                if (col + 1 < D_) {
                    float2 o = make_float2(v0 + __ldg(&bq[col]),
                                           v1 + __ldg(&bq[col + 1]));
                    *reinterpret_cast<float2*>(&q[(size_t)row * QP_ + col]) = o;
                } else if (col >= D_ && col + 1 < 2 * D_) {
                    float2 o = make_float2(v0 + __ldg(&bk[col - D_]),
                                           v1 + __ldg(&bk[col - D_ + 1]));
                    *reinterpret_cast<float2*>(&kk[(size_t)row * QP_ + 1 + (col - D_)]) = o;
                } else if (col >= 2 * D_ && col + 1 < 3 * D_) {
                    *reinterpret_cast<float2*>(&hid[(size_t)row * QP_ + (col - 2 * D_)]) =
                        make_float2(v0, v1);
                } else {
                    #pragma unroll
                    for (int e = 0; e < 2; e++) {
                        const int c = col + e;
                        const float v = e ? v1 : v0;
                        if (c < D_)
                            q[(size_t)row * QP_ + c] = v + __ldg(&bq[c]);
                        else if (c < 2 * D_)
                            kk[(size_t)row * QP_ + 1 + (c - D_)] = v + __ldg(&bk[c - D_]);
                        else if (c < 3 * D_)
                            hid[(size_t)row * QP_ + (c - 2 * D_)] = v;
                    }
                }
            }
        }
    }
}

// ---------------- pack q/k: q -> hi/lo, k -> hi only (8 elems/thread) -----------
__global__ __launch_bounds__(256) void pack_qk_kernel(
    const float* __restrict__ q, const float* __restrict__ k,
    __half* __restrict__ Qhi, __half* __restrict__ Qlo, __half* __restrict__ Khi)
{
    int idx = blockIdx.x * 256 + threadIdx.x;      // over BHN*16 (8 elems each)
    if (idx >= BHN * 16) return;
    const int dk0 = (idx & 15) * 8;
    const int rest = idx >> 4;
    const int n = rest & (N_ - 1);
    const int bh = rest >> 9;
    const int h = bh % H_, b = bh / H_;
    const size_t off = ((size_t)(b * N_ + n)) * QP_ + h * DK_;

    uint32_t qh[4], ql[4], kh[4];
    #pragma unroll
    for (int p = 0; p < 4; p++) {
        float qv0 = 0.f, qv1 = 0.f, kv0 = 0.f, kv1 = 0.f;
        int d0 = dk0 + p * 2, d1 = d0 + 1;
        if (d0 < DK_) { qv0 = __ldg(&q[off + d0]); kv0 = __ldg(&k[off + 1 + d0]); }
        if (d1 < DK_) { qv1 = __ldg(&q[off + d1]); kv1 = __ldg(&k[off + 1 + d1]); }
        __half2 qh2 = __floats2half2_rn(qv0, qv1);
        __half2 kh2 = __floats2half2_rn(kv0, kv1);
        __half2 ql2 = __floats2half2_rn(qv0 - __half2float(__low2half(qh2)),
                                        qv1 - __half2float(__high2half(qh2)));
        qh[p] = *reinterpret_cast<uint32_t*>(&qh2);
        ql[p] = *reinterpret_cast<uint32_t*>(&ql2);
        kh[p] = *reinterpret_cast<uint32_t*>(&kh2);
    }
    const size_t dst = (size_t)idx * 8;
    *reinterpret_cast<uint4*>(Qhi + dst) = make_uint4(qh[0], qh[1], qh[2], qh[3]);
    *reinterpret_cast<uint4*>(Qlo + dst) = make_uint4(ql[0], ql[1], ql[2], ql[3]);
    *reinterpret_cast<uint4*>(Khi + dst) = make_uint4(kh[0], kh[1], kh[2], kh[3]);
}

// ---------------- HMMA score GEMM (k-major: shared Khi tile per k-half) ----------
// S[bh] = (Qhi + Qlo) @ Khi^T, scaled by 1/sqrt(113), stored fp16 via smem staging.
// 2 stages of {Qhi(16K) | Qlo(16K) | Khi(16K)}; both terms hit the same acc.
__device__ __forceinline__ void issue_s(
    int cc, int tid, int m0, int nt0, int bh, uint32_t sb,
    const __half* __restrict__ Qhi, const __half* __restrict__ Qlo,
    const __half* __restrict__ Khi)
{
    const int kk0 = cc * 64;
    const size_t base = (size_t)bh * N_ * SKP;
    const uint32_t st = sb + cc * SSTAGE_B;
    #pragma unroll
    for (int it = 0; it < 4; it++) {               // Qhi: 1024 x 16B
        int i = tid + it * 256;
        int r = i >> 3, u = i & 7;
        const __half* src = Qhi + base + (size_t)(m0 + r) * SKP + kk0 + u * 8;
        cpa16(st + r * 128 + (((u ^ (r & 7))) << 4), src);
    }
    #pragma unroll
    for (int it = 0; it < 4; it++) {               // Qlo: 1024 x 16B
        int i = tid + it * 256;
        int r = i >> 3, u = i & 7;
        const __half* src = Qlo + base + (size_t)(m0 + r) * SKP + kk0 + u * 8;
        cpa16(st + 16384 + r * 128 + (((u ^ (r & 7))) << 4), src);
    }
    #pragma unroll
    for (int it = 0; it < 4; it++) {               // Khi: 1024 x 16B
        int i = tid + it * 256;
        int r = i >> 3, u = i & 7;
        const __half* src = Khi + base + (size_t)(nt0 + r) * SKP + kk0 + u * 8;
        cpa16(st + 32768 + r * 128 + (((u ^ (r & 7))) << 4), src);
    }
    asm volatile("cp.async.commit_group;" ::: "memory");
}

__global__ __launch_bounds__(256, 2) void score_hmma_kernel(
    const __half* __restrict__ Qhi, const __half* __restrict__ Qlo,
    const __half* __restrict__ Khi, __half* __restrict__ S)
{
    extern __shared__ char smc[];
    char* smb = (char*)(((uintptr_t)smc + 127) & ~(uintptr_t)127);
    const uint32_t sb = smem_u32(smb);
    const int tid = threadIdx.x;
    const int wid = tid >> 5, lane = tid & 31;
    const int m0 = blockIdx.y * 128;
    const int nt0 = blockIdx.x * 128;
    const int bh = blockIdx.z;

    float acc[2][8][4];
    #pragma unroll
    for (int t = 0; t < 2; t++)
        #pragma unroll
        for (int j = 0; j < 8; j++)
            #pragma unroll
            for (int e = 0; e < 4; e++) acc[t][j][e] = 0.f;

    issue_s(0, tid, m0, nt0, bh, sb, Qhi, Qlo, Khi);
    issue_s(1, tid, m0, nt0, bh, sb, Qhi, Qlo, Khi);

    const int warp_m = wid & 3, warp_n = wid >> 2;
    const int rowinA = (lane & 7) + ((lane >> 3) & 1) * 8;
    const int hbA    = lane >> 4;
    const int rowinB = (lane & 7) + ((lane >> 4) & 1) * 8;
    const int hbB    = (lane >> 3) & 1;

    #pragma unroll
    for (int cc = 0; cc < 2; cc++) {
        if (cc == 0) asm volatile("cp.async.wait_group 1;" ::: "memory");
        else         asm volatile("cp.async.wait_group 0;" ::: "memory");
        __syncthreads();

        const uint32_t st = sb + cc * SSTAGE_B;
        #pragma unroll
        for (int s = 0; s < 4; s++) {
            uint32_t ah[2][4], al[2][4], b[8][2];
            #pragma unroll
            for (int t = 0; t < 2; t++) {
                int r = warp_m * 32 + t * 16 + rowinA;
                uint32_t byteoff = r * 128 + ((((s << 1) | hbA) ^ (r & 7)) << 4);
                ldm4(ah[t][0], ah[t][1], ah[t][2], ah[t][3], st + byteoff);
                ldm4(al[t][0], al[t][1], al[t][2], al[t][3], st + 16384 + byteoff);
            }
            #pragma unroll
            for (int jj = 0; jj < 4; jj++) {
                int r = warp_n * 64 + jj * 16 + rowinB;
                uint32_t ad = st + 32768 + r * 128 + ((((s << 1) | hbB) ^ (r & 7)) << 4);
                ldm4(b[2 * jj][0], b[2 * jj][1], b[2 * jj + 1][0], b[2 * jj + 1][1], ad);
            }
            #pragma unroll
            for (int t = 0; t < 2; t++)
                #pragma unroll
                for (int j = 0; j < 8; j++) {
                    mma16816(acc[t][j], ah[t], b[j]);
                    mma16816(acc[t][j], al[t], b[j]);
                }
        }
        __syncthreads();
    }

    // ---- fp16 epilogue: stage 128x128 half tile in smem, write coalesced ----
    const float scale = rsqrtf((float)DK_);
    #pragma unroll
    for (int t = 0; t < 2; t++) {
        const int rl0 = warp_m * 32 + t * 16 + (lane >> 2);
        #pragma unroll
        for (int j = 0; j < 8; j++) {
            const int cl = warp_n * 64 + j * 8 + (lane & 3) * 2;
            #pragma unroll
            for (int half = 0; half < 2; half++) {
                const int rl = rl0 + half * 8;
                __half2 hv = __floats2half2_rn(acc[t][j][half * 2] * scale,
                                               acc[t][j][half * 2 + 1] * scale);
                *reinterpret_cast<uint32_t*>(smb + rl * EPI_STRIDE + cl * 2) =
                    *reinterpret_cast<uint32_t*>(&hv);
            }
        }
    }
    __syncthreads();

    // 256 threads x (1 row-half of 128B each): fully coalesced fp16 stores
    {
        const int row = tid >> 1, seg = tid & 1;
        const char* src = smb + row * EPI_STRIDE + seg * 128;
        __half* dst = S + (size_t)bh * N_ * N_ + (size_t)(m0 + row) * N_ + nt0 + seg * 64;
        #pragma unroll
        for (int u = 0; u < 8; u++)
            *reinterpret_cast<uint4*>(dst + u * 8) =
                *reinterpret_cast<const uint4*>(src + u * 16);
    }
}

// ---------------- softmax + head-sum -> attn (fp16 S input) ----------------------
__global__ __launch_bounds__(256) void softmax_kernel(
    const __half* __restrict__ S, float* __restrict__ attn)
{
    __shared__ float e[H_][N_];
    __shared__ float winv[H_];

    const int tid = threadIdx.x;
    const int wid = tid >> 5, lane = tid & 31;
    const int ng = blockIdx.x;
    const int b = ng >> 9, n = ng & (N_ - 1);

    if (wid < H_) {
        const __half2* Sr2 = reinterpret_cast<const __half2*>(
            S + ((size_t)(b * H_ + wid) * N_ + n) * N_);
        float v[16];
        float mx = -FLT_MAX;
        #pragma unroll
        for (int it = 0; it < 8; it++) {
            float2 f = __half22float2(Sr2[lane + it * 32]);
            v[2 * it] = f.x;
            v[2 * it + 1] = f.y;
            mx = fmaxf(mx, fmaxf(f.x, f.y));
        }
        #pragma unroll
        for (int o = 16; o > 0; o >>= 1) mx = fmaxf(mx, __shfl_xor_sync(0xFFFFFFFFu, mx, o));
        float sum = 0.f;
        #pragma unroll
        for (int it = 0; it < 8; it++) {
            float e0 = __expf(v[2 * it] - mx);
            float e1 = __expf(v[2 * it + 1] - mx);
            e[wid][(lane + it * 32) * 2]     = e0;
            e[wid][(lane + it * 32) * 2 + 1] = e1;
            sum += e0 + e1;
        }
        #pragma unroll
        for (int o = 16; o > 0; o >>= 1) sum += __shfl_xor_sync(0xFFFFFFFFu, sum, o);
        if (lane == 0) winv[wid] = __frcp_rn(sum);
    }
    __syncthreads();

    float* an = attn + (size_t)ng * N_;
    for (int m = tid; m < N_; m += 256) {
        float a = 0.f;
        #pragma unroll
        for (int h = 0; h < H_; h++) a += e[h][m] * winv[h];
        an[m] = a;
    }
}

// ---------------- per-batch top-2 threshold + positions -------------------------
__global__ __launch_bounds__(256) void top2_kernel(
    const float* __restrict__ attn, int* __restrict__ pos, int* __restrict__ cnt)
{
    __shared__ float v1s[256], v2s[256];
    __shared__ float s_kth;
    __shared__ int   s_cnt;

    const int b = blockIdx.x;
    const int tid = threadIdx.x;
    const float* A = attn + (size_t)b * N_ * N_;

    float v1 = -FLT_MAX, v2 = -FLT_MAX;
    for (int i = tid; i < N_ * N_; i += 256) {
        float v = A[i];
        if (v > v1) { v2 = v1; v1 = v; }
        else if (v > v2) v2 = v;
    }
    v1s[tid] = v1; v2s[tid] = v2;
    __syncthreads();
    if (tid == 0) {
        float t1 = -FLT_MAX, t2 = -FLT_MAX;
        for (int i = 0; i < 256; i++) {
            float a = v1s[i], c = v2s[i];
            if (a > t1) { t2 = t1; t1 = a; } else if (a > t2) t2 = a;
            if (c > t1) { t2 = t1; t1 = c; } else if (c > t2) t2 = c;
        }
        s_kth = t2;
        s_cnt = 0;
    }
    __syncthreads();
    const float kth = s_kth;
    const int base = b * MAXP * 2;
    for (int i = tid; i < N_ * N_; i += 256) {
        if (A[i] >= kth) {
            int idx = atomicAdd(&s_cnt, 1);
            if (idx < MAXP) {
                pos[base + idx * 2]     = i >> 9;
                pos[base + idx * 2 + 1] = i & (N_ - 1);
            }
        }
    }
    __syncthreads();
    if (tid == 0) {
        int c = s_cnt < MAXP ? s_cnt : MAXP;
        for (int a2 = 1; a2 < c; a2++) {
            int ki = pos[base + a2 * 2], kj = pos[base + a2 * 2 + 1];
            int key = ki * N_ + kj;
            int p = a2 - 1;
            while (p >= 0) {
                int pi = pos[base + p * 2], pj = pos[base + p * 2 + 1];
                if (pi * N_ + pj <= key) break;
                pos[base + (p + 1) * 2] = pi;
                pos[base + (p + 1) * 2 + 1] = pj;
                p--;
            }
            pos[base + (p + 1) * 2] = ki;
            pos[base + (p + 1) * 2 + 1] = kj;
        }
        cnt[b] = c;
    }
}

// ---------------- sparse adjacency apply + GC epilogue --------------------------
__global__ __launch_bounds__(256) void out_kernel(
    const float* __restrict__ attn, const float* __restrict__ hidden,
    const float* __restrict__ bgc, const int* __restrict__ pos,
    const int* __restrict__ cnt, float* __restrict__ out)
{
    const int b = blockIdx.y;
    const int n = blockIdx.x;
    const int tid = threadIdx.x;

    __shared__ int   s_nc;
    __shared__ int   s_cols[2 * MAXP];
    __shared__ float s_w[2 * MAXP];
    __shared__ float s_wd, s_inv;

    if (tid == 0) {
        const float* An = attn + ((size_t)b * N_ + n) * N_;
        const int base = b * MAXP * 2;
        int c = cnt[b];
        int nc = 0;
        float wd = An[n];
        float sum = wd;
        for (int e = 0; e < c; e++) {
            int i = pos[base + e * 2], j = pos[base + e * 2 + 1];
            if (i == n && j != n) { float w = An[j]; s_cols[nc] = j; s_w[nc] = w; sum += w; nc++; }
            if (j == n && i != n) { float w = An[i]; s_cols[nc] = i; s_w[nc] = w; sum += w; nc++; }
        }
        s_nc = nc; s_wd = wd; s_inv = 1.f / (sum + 1.f);
    }
    __syncthreads();

    const int nc = s_nc;
    const float wd = s_wd, inv = s_inv;
    const float* hn = hidden + ((size_t)b * N_ + n) * QP_;
    float* on = out + ((size_t)b * N_ + n) * D_;

    for (int d = tid; d < D_; d += 256) {
        float v = wd * hn[d];
        for (int e = 0; e < nc; e++)
            v += s_w[e] * hidden[((size_t)b * N_ + s_cols[e]) * QP_ + d];
        v = v * inv + __ldg(&bgc[d]);
        on[d] = fmaxf(v, 0.f);
    }
}

// ---------------- launch ------------------------------------------------------
extern "C" void kernel_launch(void* const* d_in, const int* in_sizes, int n_in,
                              void* d_out, int out_size)
{
    const float* fuse = (const float*)d_in[0];
    const float* Wq   = (const float*)d_in[1];
    const float* bq   = (const float*)d_in[2];
    const float* Wk   = (const float*)d_in[3];
    const float* bk   = (const float*)d_in[4];
    const float* Wgc  = (const float*)d_in[5];
    const float* bgc  = (const float*)d_in[6];
    float* out = (float*)d_out;

    __half *Ahi, *Bh, *Qhi, *Qlo, *Khi, *S;
    float *q, *k, *hid, *attn;
    int *pos, *cnt;
    cudaGetSymbolAddress((void**)&Ahi,  g_Ahi);
    cudaGetSymbolAddress((void**)&Bh,   g_Bh);
    cudaGetSymbolAddress((void**)&Qhi,  g_Qhi);
    cudaGetSymbolAddress((void**)&Qlo,  g_Qlo);
    cudaGetSymbolAddress((void**)&Khi,  g_Khi);
    cudaGetSymbolAddress((void**)&S,    g_S);
    cudaGetSymbolAddress((void**)&q,    g_q);
    cudaGetSymbolAddress((void**)&k,    g_k);
    cudaGetSymbolAddress((void**)&hid,  g_h);
    cudaGetSymbolAddress((void**)&attn, g_attn);
    cudaGetSymbolAddress((void**)&pos,  g_pos);
    cudaGetSymbolAddress((void**)&cnt,  g_cnt);

    // 0) fp16 conversions: A hi-only (vectorized); B via coalesced transpose
    convA_kernel<<<(M_ * KP_ / 4 + 255) / 256, 256>>>(fuse, Ahi);
    transB_kernel<<<dim3(KP_ / 32, (D_ + 31) / 32, 3), 256>>>(Wq, Wk, Wgc, Bh);

    // 1) fused HMMA GEMM (hi term only, 2 CTA/SM) -> q, k, hidden (stride 792)
    cudaFuncSetAttribute(gemm_hmma_kernel, cudaFuncAttributeMaxDynamicSharedMemorySize, GEMM_SMEM);
    gemm_hmma_kernel<<<dim3(NPAD_ / 128, M_ / 128), 256, GEMM_SMEM>>>(
        Ahi, Bh, bq, bk, q, k, hid);

    // 2) pack q (hi/lo) and k (hi) head-padded fp16 (vectorized)
    pack_qk_kernel<<<(BHN * 16 + 255) / 256, 256>>>(q, k, Qhi, Qlo, Khi);

    // 3) HMMA score GEMM (k-major, shared Khi, 2 CTA/SM) -> S[B,H,N,N] fp16
    cudaFuncSetAttribute(score_hmma_kernel, cudaFuncAttributeMaxDynamicSharedMemorySize, SGEMM_SMEM);
    score_hmma_kernel<<<dim3(N_ / 128, N_ / 128, B_ * H_), 256, SGEMM_SMEM>>>(
        Qhi, Qlo, Khi, S);

    // 4) softmax + head-sum -> attn
    softmax_kernel<<<M_, 256>>>(S, attn);

    // 5) per-batch top-2 threshold + sparse positions
    top2_kernel<<<B_, 256>>>(attn, pos, cnt);

    // 6) sparse adjacency apply + graph-conv epilogue
    out_kernel<<<dim3(N_, B_), 256>>>(attn, hid, bgc, pos, cnt, out);
}

// round 16
// speedup vs baseline: 1.3051x; 1.2252x over previous
#include <cuda_runtime.h>
#include <cuda_fp16.h>
#include <cfloat>
#include <cstdint>

// Problem constants
#define B_   32
#define N_   512
#define D_   791
#define H_   7
#define DK_  113
#define M_   (B_ * N_)     // 16384
#define MAXP 64
#define QP_  792            // padded row stride for q/k/hid (fp32), 8B-aligned pairs

// main HMMA GEMM: CTA 128x128, warp tile 32x64, 8 warps, 3-stage, 2 CTA/SM
#define KP_     832          // padded K (13 * 64)
#define NCH     13           // single hi term, 13 chunks of K=64
#define NPAD_   2432         // fused N = 3*791 = 2373 padded to 19*128
#define STAGE_B 32768        // A 128x64 fp16 (16KB) + B 128x64 fp16 (16KB)
#define GEMM_SMEM (3 * STAGE_B + 256)
#define BHN (B_ * H_ * N_)   // 114688 packed rows

// score GEMM: CTA 128x128, 2 k-half stages of {Qhi,Qlo,Khi} (48KB each)
#define SKP   128
#define SSTAGE_B 49152
#define SGEMM_SMEM (2 * SSTAGE_B + 256)
#define EPI_STRIDE 272       // fp16 staging row stride (bytes): 16B-aligned, conflict-free

// ---------------- scratch (device globals; no allocation allowed) -------------
__device__ __align__(256) __half g_Ahi[M_ * KP_];
__device__ __align__(256) __half g_Bh [NPAD_ * KP_];   // zero-init; transB fills n<791
__device__ __align__(256) __half g_Qhi[(size_t)BHN * SKP];
__device__ __align__(256) __half g_Qlo[(size_t)BHN * SKP];
__device__ __align__(256) __half g_Khi[(size_t)BHN * SKP];
__device__ __align__(256) __half g_S[(size_t)B_ * H_ * N_ * N_];
__device__ __align__(256) float g_q[(size_t)M_ * QP_];
__device__ __align__(256) float g_k[(size_t)M_ * QP_];
__device__ __align__(256) float g_h[(size_t)M_ * QP_];
__device__ float g_attn[B_ * N_ * N_];
__device__ float g_rowv[M_ * 2];     // per-row top-2 values
__device__ int   g_rowp[M_ * 2];     // per-row top-2 positions
__device__ int   g_pos[B_ * MAXP * 2];
__device__ int   g_cnt[B_];

// ---------------- PTX helpers --------------------------------------------------
__device__ __forceinline__ uint32_t smem_u32(const void* p) {
    uint32_t a;
    asm("{ .reg .u64 t; cvta.to.shared.u64 t, %1; cvt.u32.u64 %0, t; }" : "=r"(a) : "l"(p));
    return a;
}
__device__ __forceinline__ void ldm4(uint32_t& r0, uint32_t& r1, uint32_t& r2,
                                     uint32_t& r3, uint32_t a) {
    asm volatile("ldmatrix.sync.aligned.m8n8.x4.shared.b16 {%0,%1,%2,%3}, [%4];"
                 : "=r"(r0), "=r"(r1), "=r"(r2), "=r"(r3) : "r"(a));
}
__device__ __forceinline__ void mma16816(float* d, const uint32_t* a, const uint32_t* b) {
    asm volatile(
        "mma.sync.aligned.m16n8k16.row.col.f32.f16.f16.f32 "
        "{%0,%1,%2,%3}, {%4,%5,%6,%7}, {%8,%9}, {%0,%1,%2,%3};"
        : "+f"(d[0]), "+f"(d[1]), "+f"(d[2]), "+f"(d[3])
        : "r"(a[0]), "r"(a[1]), "r"(a[2]), "r"(a[3]), "r"(b[0]), "r"(b[1]));
}
__device__ __forceinline__ void cpa16(uint32_t dst, const void* src) {
    asm volatile("cp.async.cg.shared.global [%0], [%1], 16;" :: "r"(dst), "l"(src));
}

// ---------------- conversions ----------------------------------------------------
__global__ __launch_bounds__(256) void convA_kernel(
    const float* __restrict__ fuse, __half* __restrict__ Ahi)
{
    int idx = blockIdx.x * 256 + threadIdx.x;      // over M_*KP_/4
    if (idx >= M_ * KP_ / 4) return;
    int m = idx / (KP_ / 4);
    int k = (idx - m * (KP_ / 4)) * 4;
    const float* src = fuse + (size_t)m * D_ + k;
    float x0 = (k     < D_) ? __ldg(src)     : 0.f;
    float x1 = (k + 1 < D_) ? __ldg(src + 1) : 0.f;
    float x2 = (k + 2 < D_) ? __ldg(src + 2) : 0.f;
    float x3 = (k + 3 < D_) ? __ldg(src + 3) : 0.f;
    __half2 h01 = __floats2half2_rn(x0, x1);
    __half2 h23 = __floats2half2_rn(x2, x3);
    uint2 o;
    o.x = *reinterpret_cast<uint32_t*>(&h01);
    o.y = *reinterpret_cast<uint32_t*>(&h23);
    *reinterpret_cast<uint2*>(Ahi + (size_t)idx * 4) = o;
}

// Coalesced transpose: Bh[z*791 + n][k] = W_z[k][n], 32x32 smem tiles.
__global__ __launch_bounds__(256) void transB_kernel(
    const float* __restrict__ Wq, const float* __restrict__ Wk,
    const float* __restrict__ Wgc, __half* __restrict__ Bh)
{
    __shared__ __half tile[32][33];
    const int z = blockIdx.z;
    const float* W = (z == 0) ? Wq : (z == 1) ? Wk : Wgc;
    const int k0 = blockIdx.x * 32;
    const int n0 = blockIdx.y * 32;
    const int tx = threadIdx.x & 31, ty = threadIdx.x >> 5;

    #pragma unroll
    for (int rr = 0; rr < 4; rr++) {
        int k = k0 + ty + rr * 8;
        int n = n0 + tx;
        float v = (k < D_ && n < D_) ? W[(size_t)k * D_ + n] : 0.f;
        tile[ty + rr * 8][tx] = __float2half_rn(v);
    }
    __syncthreads();
    #pragma unroll
    for (int rr = 0; rr < 4; rr++) {
        int n = n0 + ty + rr * 8;
        int k = k0 + tx;
        if (n < D_ && k < KP_)
            Bh[(size_t)(z * D_ + n) * KP_ + k] = tile[tx][ty + rr * 8];
    }
}

// ---------------- HMMA fused GEMM (single hi term, 128x128, 3-stage) -------------
__device__ __forceinline__ void issue_chunk(
    int cc, int tid, int m0, int nt0, uint32_t sb,
    const __half* __restrict__ Ahi, const __half* __restrict__ Bh)
{
    const int kk0 = cc * 64;
    const uint32_t st = sb + (cc % 3) * STAGE_B;
    #pragma unroll
    for (int it = 0; it < 4; it++) {               // A: 1024 x 16B
        int i = tid + it * 256;
        int r = i >> 3, u = i & 7;
        const __half* src = Ahi + (size_t)(m0 + r) * KP_ + kk0 + u * 8;
        cpa16(st + r * 128 + (((u ^ (r & 7))) << 4), src);
    }
    #pragma unroll
    for (int it = 0; it < 4; it++) {               // B: 1024 x 16B
        int i = tid + it * 256;
        int r = i >> 3, u = i & 7;
        const __half* src = Bh + (size_t)(nt0 + r) * KP_ + kk0 + u * 8;
        cpa16(st + 16384 + r * 128 + (((u ^ (r & 7))) << 4), src);
    }
    asm volatile("cp.async.commit_group;" ::: "memory");
}

__global__ __launch_bounds__(256, 2) void gemm_hmma_kernel(
    const __half* __restrict__ Ahi, const __half* __restrict__ Bh,
    const float* __restrict__ bq, const float* __restrict__ bk,
    float* __restrict__ q, float* __restrict__ kk, float* __restrict__ hid)
{
    extern __shared__ char smc[];
    const uint32_t sb = (smem_u32(smc) + 127) & ~127u;
    const int tid = threadIdx.x;
    const int wid = tid >> 5, lane = tid & 31;
    const int m0 = blockIdx.y * 128;
    const int nt0 = blockIdx.x * 128;

    float acc[2][8][4];
    #pragma unroll
    for (int t = 0; t < 2; t++)
        #pragma unroll
        for (int j = 0; j < 8; j++)
            #pragma unroll
            for (int e = 0; e < 4; e++) acc[t][j][e] = 0.f;

    issue_chunk(0, tid, m0, nt0, sb, Ahi, Bh);
    issue_chunk(1, tid, m0, nt0, sb, Ahi, Bh);

    const int warp_m = wid & 3, warp_n = wid >> 2;
    const int rowinA = (lane & 7) + ((lane >> 3) & 1) * 8;
    const int hbA    = lane >> 4;
    const int rowinB = (lane & 7) + ((lane >> 4) & 1) * 8;
    const int hbB    = (lane >> 3) & 1;

    for (int cc = 0; cc < NCH; cc++) {
        if (cc == NCH - 1) asm volatile("cp.async.wait_group 0;" ::: "memory");
        else               asm volatile("cp.async.wait_group 1;" ::: "memory");
        __syncthreads();
        if (cc + 2 < NCH) issue_chunk(cc + 2, tid, m0, nt0, sb, Ahi, Bh);

        const uint32_t st = sb + (cc % 3) * STAGE_B;
        #pragma unroll
        for (int s = 0; s < 4; s++) {
            uint32_t a[2][4], b[8][2];
            #pragma unroll
            for (int t = 0; t < 2; t++) {
                int r = warp_m * 32 + t * 16 + rowinA;
                uint32_t ad = st + r * 128 + ((((s << 1) | hbA) ^ (r & 7)) << 4);
                ldm4(a[t][0], a[t][1], a[t][2], a[t][3], ad);
            }
            #pragma unroll
            for (int jj = 0; jj < 4; jj++) {
                int r = warp_n * 64 + jj * 16 + rowinB;
                uint32_t ad = st + 16384 + r * 128 + ((((s << 1) | hbB) ^ (r & 7)) << 4);
                ldm4(b[2 * jj][0], b[2 * jj][1], b[2 * jj + 1][0], b[2 * jj + 1][1], ad);
            }
            #pragma unroll
            for (int t = 0; t < 2; t++)
                #pragma unroll
                for (int j = 0; j < 8; j++)
                    mma16816(acc[t][j], a[t], b[j]);
        }
    }

    // epilogue: demux to q | k | hid with bias. Row stride QP_=792; k at +1 base.
    #pragma unroll
    for (int t = 0; t < 2; t++) {
        const int row0 = m0 + warp_m * 32 + t * 16 + (lane >> 2);
        #pragma unroll
        for (int j = 0; j < 8; j++) {
            const int col = nt0 + warp_n * 64 + j * 8 + (lane & 3) * 2;
            #pragma unroll
            for (int half = 0; half < 2; half++) {
                const int row = row0 + half * 8;
                const float v0 = acc[t][j][half * 2];
                const float v1 = acc[t][j][half * 2 + 1];
                if (col + 1 < D_) {
                    float2 o = make_float2(v0 + __ldg(&bq[col]),
                                           v1 + __ldg(&bq[col + 1]));
                    *reinterpret_cast<float2*>(&q[(size_t)row * QP_ + col]) = o;
                } else if (col >= D_ && col + 1 < 2 * D_) {
                    float2 o = make_float2(v0 + __ldg(&bk[col - D_]),
                                           v1 + __ldg(&bk[col - D_ + 1]));
                    *reinterpret_cast<float2*>(&kk[(size_t)row * QP_ + 1 + (col - D_)]) = o;
                } else if (col >= 2 * D_ && col + 1 < 3 * D_) {
                    *reinterpret_cast<float2*>(&hid[(size_t)row * QP_ + (col - 2 * D_)]) =
                        make_float2(v0, v1);
                } else {
                    #pragma unroll
                    for (int e = 0; e < 2; e++) {
                        const int c = col + e;
                        const float v = e ? v1 : v0;
                        if (c < D_)
                            q[(size_t)row * QP_ + c] = v + __ldg(&bq[c]);
                        else if (c < 2 * D_)
                            kk[(size_t)row * QP_ + 1 + (c - D_)] = v + __ldg(&bk[c - D_]);
                        else if (c < 3 * D_)
                            hid[(size_t)row * QP_ + (c - 2 * D_)] = v;
                    }
                }
            }
        }
    }
}

// ---------------- pack q/k: q -> hi/lo, k -> hi only (8 elems/thread) -----------
__global__ __launch_bounds__(256) void pack_qk_kernel(
    const float* __restrict__ q, const float* __restrict__ k,
    __half* __restrict__ Qhi, __half* __restrict__ Qlo, __half* __restrict__ Khi)
{
    int idx = blockIdx.x * 256 + threadIdx.x;      // over BHN*16 (8 elems each)
    if (idx >= BHN * 16) return;
    const int dk0 = (idx & 15) * 8;
    const int rest = idx >> 4;
    const int n = rest & (N_ - 1);
    const int bh = rest >> 9;
    const int h = bh % H_, b = bh / H_;
    const size_t off = ((size_t)(b * N_ + n)) * QP_ + h * DK_;

    uint32_t qh[4], ql[4], kh[4];
    #pragma unroll
    for (int p = 0; p < 4; p++) {
        float qv0 = 0.f, qv1 = 0.f, kv0 = 0.f, kv1 = 0.f;
        int d0 = dk0 + p * 2, d1 = d0 + 1;
        if (d0 < DK_) { qv0 = __ldg(&q[off + d0]); kv0 = __ldg(&k[off + 1 + d0]); }
        if (d1 < DK_) { qv1 = __ldg(&q[off + d1]); kv1 = __ldg(&k[off + 1 + d1]); }
        __half2 qh2 = __floats2half2_rn(qv0, qv1);
        __half2 kh2 = __floats2half2_rn(kv0, kv1);
        __half2 ql2 = __floats2half2_rn(qv0 - __half2float(__low2half(qh2)),
                                        qv1 - __half2float(__high2half(qh2)));
        qh[p] = *reinterpret_cast<uint32_t*>(&qh2);
        ql[p] = *reinterpret_cast<uint32_t*>(&ql2);
        kh[p] = *reinterpret_cast<uint32_t*>(&kh2);
    }
    const size_t dst = (size_t)idx * 8;
    *reinterpret_cast<uint4*>(Qhi + dst) = make_uint4(qh[0], qh[1], qh[2], qh[3]);
    *reinterpret_cast<uint4*>(Qlo + dst) = make_uint4(ql[0], ql[1], ql[2], ql[3]);
    *reinterpret_cast<uint4*>(Khi + dst) = make_uint4(kh[0], kh[1], kh[2], kh[3]);
}

// ---------------- HMMA score GEMM (k-major: shared Khi tile per k-half) ----------
__device__ __forceinline__ void issue_s(
    int cc, int tid, int m0, int nt0, int bh, uint32_t sb,
    const __half* __restrict__ Qhi, const __half* __restrict__ Qlo,
    const __half* __restrict__ Khi)
{
    const int kk0 = cc * 64;
    const size_t base = (size_t)bh * N_ * SKP;
    const uint32_t st = sb + cc * SSTAGE_B;
    #pragma unroll
    for (int it = 0; it < 4; it++) {               // Qhi: 1024 x 16B
        int i = tid + it * 256;
        int r = i >> 3, u = i & 7;
        const __half* src = Qhi + base + (size_t)(m0 + r) * SKP + kk0 + u * 8;
        cpa16(st + r * 128 + (((u ^ (r & 7))) << 4), src);
    }
    #pragma unroll
    for (int it = 0; it < 4; it++) {               // Qlo: 1024 x 16B
        int i = tid + it * 256;
        int r = i >> 3, u = i & 7;
        const __half* src = Qlo + base + (size_t)(m0 + r) * SKP + kk0 + u * 8;
        cpa16(st + 16384 + r * 128 + (((u ^ (r & 7))) << 4), src);
    }
    #pragma unroll
    for (int it = 0; it < 4; it++) {               // Khi: 1024 x 16B
        int i = tid + it * 256;
        int r = i >> 3, u = i & 7;
        const __half* src = Khi + base + (size_t)(nt0 + r) * SKP + kk0 + u * 8;
        cpa16(st + 32768 + r * 128 + (((u ^ (r & 7))) << 4), src);
    }
    asm volatile("cp.async.commit_group;" ::: "memory");
}

__global__ __launch_bounds__(256, 2) void score_hmma_kernel(
    const __half* __restrict__ Qhi, const __half* __restrict__ Qlo,
    const __half* __restrict__ Khi, __half* __restrict__ S)
{
    extern __shared__ char smc[];
    char* smb = (char*)(((uintptr_t)smc + 127) & ~(uintptr_t)127);
    const uint32_t sb = smem_u32(smb);
    const int tid = threadIdx.x;
    const int wid = tid >> 5, lane = tid & 31;
    const int m0 = blockIdx.y * 128;
    const int nt0 = blockIdx.x * 128;
    const int bh = blockIdx.z;

    float acc[2][8][4];
    #pragma unroll
    for (int t = 0; t < 2; t++)
        #pragma unroll
        for (int j = 0; j < 8; j++)
            #pragma unroll
            for (int e = 0; e < 4; e++) acc[t][j][e] = 0.f;

    issue_s(0, tid, m0, nt0, bh, sb, Qhi, Qlo, Khi);
    issue_s(1, tid, m0, nt0, bh, sb, Qhi, Qlo, Khi);

    const int warp_m = wid & 3, warp_n = wid >> 2;
    const int rowinA = (lane & 7) + ((lane >> 3) & 1) * 8;
    const int hbA    = lane >> 4;
    const int rowinB = (lane & 7) + ((lane >> 4) & 1) * 8;
    const int hbB    = (lane >> 3) & 1;

    #pragma unroll
    for (int cc = 0; cc < 2; cc++) {
        if (cc == 0) asm volatile("cp.async.wait_group 1;" ::: "memory");
        else         asm volatile("cp.async.wait_group 0;" ::: "memory");
        __syncthreads();

        const uint32_t st = sb + cc * SSTAGE_B;
        #pragma unroll
        for (int s = 0; s < 4; s++) {
            uint32_t ah[2][4], al[2][4], b[8][2];
            #pragma unroll
            for (int t = 0; t < 2; t++) {
                int r = warp_m * 32 + t * 16 + rowinA;
                uint32_t byteoff = r * 128 + ((((s << 1) | hbA) ^ (r & 7)) << 4);
                ldm4(ah[t][0], ah[t][1], ah[t][2], ah[t][3], st + byteoff);
                ldm4(al[t][0], al[t][1], al[t][2], al[t][3], st + 16384 + byteoff);
            }
            #pragma unroll
            for (int jj = 0; jj < 4; jj++) {
                int r = warp_n * 64 + jj * 16 + rowinB;
                uint32_t ad = st + 32768 + r * 128 + ((((s << 1) | hbB) ^ (r & 7)) << 4);
                ldm4(b[2 * jj][0], b[2 * jj][1], b[2 * jj + 1][0], b[2 * jj + 1][1], ad);
            }
            #pragma unroll
            for (int t = 0; t < 2; t++)
                #pragma unroll
                for (int j = 0; j < 8; j++) {
                    mma16816(acc[t][j], ah[t], b[j]);
                    mma16816(acc[t][j], al[t], b[j]);
                }
        }
        __syncthreads();
    }

    // ---- fp16 epilogue: stage 128x128 half tile in smem, write coalesced ----
    const float scale = rsqrtf((float)DK_);
    #pragma unroll
    for (int t = 0; t < 2; t++) {
        const int rl0 = warp_m * 32 + t * 16 + (lane >> 2);
        #pragma unroll
        for (int j = 0; j < 8; j++) {
            const int cl = warp_n * 64 + j * 8 + (lane & 3) * 2;
            #pragma unroll
            for (int half = 0; half < 2; half++) {
                const int rl = rl0 + half * 8;
                __half2 hv = __floats2half2_rn(acc[t][j][half * 2] * scale,
                                               acc[t][j][half * 2 + 1] * scale);
                *reinterpret_cast<uint32_t*>(smb + rl * EPI_STRIDE + cl * 2) =
                    *reinterpret_cast<uint32_t*>(&hv);
            }
        }
    }
    __syncthreads();

    {
        const int row = tid >> 1, seg = tid & 1;
        const char* src = smb + row * EPI_STRIDE + seg * 128;
        __half* dst = S + (size_t)bh * N_ * N_ + (size_t)(m0 + row) * N_ + nt0 + seg * 64;
        #pragma unroll
        for (int u = 0; u < 8; u++)
            *reinterpret_cast<uint4*>(dst + u * 8) =
                *reinterpret_cast<const uint4*>(src + u * 16);
    }
}

// ---------------- softmax + head-sum -> attn + per-row top-2 ---------------------
__global__ __launch_bounds__(256) void softmax_kernel(
    const __half* __restrict__ S, float* __restrict__ attn,
    float* __restrict__ rowv, int* __restrict__ rowp)
{
    __shared__ float e[H_][N_];
    __shared__ float winv[H_];
    __shared__ float wv1[8], wv2[8];
    __shared__ int   wp1[8], wp2[8];

    const int tid = threadIdx.x;
    const int wid = tid >> 5, lane = tid & 31;
    const int ng = blockIdx.x;
    const int b = ng >> 9, n = ng & (N_ - 1);

    if (wid < H_) {
        const __half2* Sr2 = reinterpret_cast<const __half2*>(
            S + ((size_t)(b * H_ + wid) * N_ + n) * N_);
        float v[16];
        float mx = -FLT_MAX;
        #pragma unroll
        for (int it = 0; it < 8; it++) {
            float2 f = __half22float2(Sr2[lane + it * 32]);
            v[2 * it] = f.x;
            v[2 * it + 1] = f.y;
            mx = fmaxf(mx, fmaxf(f.x, f.y));
        }
        #pragma unroll
        for (int o = 16; o > 0; o >>= 1) mx = fmaxf(mx, __shfl_xor_sync(0xFFFFFFFFu, mx, o));
        float sum = 0.f;
        #pragma unroll
        for (int it = 0; it < 8; it++) {
            float e0 = __expf(v[2 * it] - mx);
            float e1 = __expf(v[2 * it + 1] - mx);
            e[wid][(lane + it * 32) * 2]     = e0;
            e[wid][(lane + it * 32) * 2 + 1] = e1;
            sum += e0 + e1;
        }
        #pragma unroll
        for (int o = 16; o > 0; o >>= 1) sum += __shfl_xor_sync(0xFFFFFFFFu, sum, o);
        if (lane == 0) winv[wid] = __frcp_rn(sum);
    }
    __syncthreads();

    // head-sum + per-thread top-2
    float tv1 = -FLT_MAX, tv2 = -FLT_MAX;
    int   tp1 = 0, tp2 = 0;
    float* an = attn + (size_t)ng * N_;
    #pragma unroll
    for (int it = 0; it < 2; it++) {
        int m = tid + it * 256;
        float a = 0.f;
        #pragma unroll
        for (int h = 0; h < H_; h++) a += e[h][m] * winv[h];
        an[m] = a;
        if (a > tv1) { tv2 = tv1; tp2 = tp1; tv1 = a; tp1 = m; }
        else if (a > tv2) { tv2 = a; tp2 = m; }
    }
    // warp top-2 merge
    #pragma unroll
    for (int o = 16; o > 0; o >>= 1) {
        float ov1 = __shfl_xor_sync(0xFFFFFFFFu, tv1, o);
        float ov2 = __shfl_xor_sync(0xFFFFFFFFu, tv2, o);
        int   op1 = __shfl_xor_sync(0xFFFFFFFFu, tp1, o);
        int   op2 = __shfl_xor_sync(0xFFFFFFFFu, tp2, o);
        if (ov1 > tv1) {
            if (tv1 >= ov2) { tv2 = tv1; tp2 = tp1; }
            else            { tv2 = ov2; tp2 = op2; }
            tv1 = ov1; tp1 = op1;
        } else if (ov1 > tv2) {
            tv2 = ov1; tp2 = op1;
        }
    }
    if (lane == 0) { wv1[wid] = tv1; wv2[wid] = tv2; wp1[wid] = tp1; wp2[wid] = tp2; }
    __syncthreads();
    if (tid == 0) {
        float v1 = wv1[0], v2 = wv2[0];
        int   p1 = wp1[0], p2 = wp2[0];
        #pragma unroll
        for (int w = 1; w < 8; w++) {
            float a1 = wv1[w], a2 = wv2[w];
            int   b1 = wp1[w], b2 = wp2[w];
            if (a1 > v1) {
                if (v1 >= a2) { v2 = v1; p2 = p1; }
                else          { v2 = a2; p2 = b2; }
                v1 = a1; p1 = b1;
            } else if (a1 > v2) {
                v2 = a1; p2 = b1;
            }
        }
        rowv[ng * 2]     = v1;
        rowv[ng * 2 + 1] = v2;
        rowp[ng * 2]     = p1;
        rowp[ng * 2 + 1] = p2;
    }
}

// ---------------- per-batch top-2 from row candidates ---------------------------
__global__ __launch_bounds__(256) void top2_kernel(
    const float* __restrict__ rowv, const int* __restrict__ rowp,
    int* __restrict__ pos, int* __restrict__ cnt)
{
    __shared__ float v1s[256], v2s[256];
    __shared__ float s_kth;
    __shared__ int   s_cnt;

    const int b = blockIdx.x;
    const int tid = threadIdx.x;
    const float* V = rowv + b * N_ * 2;   // 1024 candidate values
    const int*   P = rowp + b * N_ * 2;

    float v1 = -FLT_MAX, v2 = -FLT_MAX;
    for (int i = tid; i < 2 * N_; i += 256) {
        float v = V[i];
        if (v > v1) { v2 = v1; v1 = v; }
        else if (v > v2) v2 = v;
    }
    v1s[tid] = v1; v2s[tid] = v2;
    __syncthreads();
    if (tid == 0) {
        float t1 = -FLT_MAX, t2 = -FLT_MAX;
        for (int i = 0; i < 256; i++) {
            float a = v1s[i], c = v2s[i];
            if (a > t1) { t2 = t1; t1 = a; } else if (a > t2) t2 = a;
            if (c > t1) { t2 = t1; t1 = c; } else if (c > t2) t2 = c;
        }
        s_kth = t2;
        s_cnt = 0;
    }
    __syncthreads();
    const float kth = s_kth;
    const int base = b * MAXP * 2;
    for (int i = tid; i < 2 * N_; i += 256) {
        if (V[i] >= kth) {
            int idx = atomicAdd(&s_cnt, 1);
            if (idx < MAXP) {
                pos[base + idx * 2]     = i >> 1;     // row
                pos[base + idx * 2 + 1] = P[i];       // col
            }
        }
    }
    __syncthreads();
    if (tid == 0) {
        int c = s_cnt < MAXP ? s_cnt : MAXP;
        for (int a2 = 1; a2 < c; a2++) {
            int ki = pos[base + a2 * 2], kj = pos[base + a2 * 2 + 1];
            int key = ki * N_ + kj;
            int p = a2 - 1;
            while (p >= 0) {
                int pi = pos[base + p * 2], pj = pos[base + p * 2 + 1];
                if (pi * N_ + pj <= key) break;
                pos[base + (p + 1) * 2] = pi;
                pos[base + (p + 1) * 2 + 1] = pj;
                p--;
            }
            pos[base + (p + 1) * 2] = ki;
            pos[base + (p + 1) * 2 + 1] = kj;
        }
        cnt[b] = c;
    }
}

// ---------------- sparse adjacency apply + GC epilogue --------------------------
__global__ __launch_bounds__(256) void out_kernel(
    const float* __restrict__ attn, const float* __restrict__ hidden,
    const float* __restrict__ bgc, const int* __restrict__ pos,
    const int* __restrict__ cnt, float* __restrict__ out)
{
    const int b = blockIdx.y;
    const int n = blockIdx.x;
    const int tid = threadIdx.x;

    __shared__ int   s_nc;
    __shared__ int   s_cols[2 * MAXP];
    __shared__ float s_w[2 * MAXP];
    __shared__ float s_wd, s_inv;

    if (tid == 0) {
        const float* An = attn + ((size_t)b * N_ + n) * N_;
        const int base = b * MAXP * 2;
        int c = cnt[b];
        int nc = 0;
        float wd = An[n];
        float sum = wd;
        for (int e = 0; e < c; e++) {
            int i = pos[base + e * 2], j = pos[base + e * 2 + 1];
            if (i == n && j != n) { float w = An[j]; s_cols[nc] = j; s_w[nc] = w; sum += w; nc++; }
            if (j == n && i != n) { float w = An[i]; s_cols[nc] = i; s_w[nc] = w; sum += w; nc++; }
        }
        s_nc = nc; s_wd = wd; s_inv = 1.f / (sum + 1.f);
    }
    __syncthreads();

    const int nc = s_nc;
    const float wd = s_wd, inv = s_inv;
    const float* hn = hidden + ((size_t)b * N_ + n) * QP_;
    float* on = out + ((size_t)b * N_ + n) * D_;

    for (int d = tid; d < D_; d += 256) {
        float v = wd * hn[d];
        for (int e = 0; e < nc; e++)
            v += s_w[e] * hidden[((size_t)b * N_ + s_cols[e]) * QP_ + d];
        v = v * inv + __ldg(&bgc[d]);
        on[d] = fmaxf(v, 0.f);
    }
}

// ---------------- launch ------------------------------------------------------
extern "C" void kernel_launch(void* const* d_in, const int* in_sizes, int n_in,
                              void* d_out, int out_size)
{
    const float* fuse = (const float*)d_in[0];
    const float* Wq   = (const float*)d_in[1];
    const float* bq   = (const float*)d_in[2];
    const float* Wk   = (const float*)d_in[3];
    const float* bk   = (const float*)d_in[4];
    const float* Wgc  = (const float*)d_in[5];
    const float* bgc  = (const float*)d_in[6];
    float* out = (float*)d_out;

    __half *Ahi, *Bh, *Qhi, *Qlo, *Khi, *S;
    float *q, *k, *hid, *attn, *rowv;
    int *rowp, *pos, *cnt;
    cudaGetSymbolAddress((void**)&Ahi,  g_Ahi);
    cudaGetSymbolAddress((void**)&Bh,   g_Bh);
    cudaGetSymbolAddress((void**)&Qhi,  g_Qhi);
    cudaGetSymbolAddress((void**)&Qlo,  g_Qlo);
    cudaGetSymbolAddress((void**)&Khi,  g_Khi);
    cudaGetSymbolAddress((void**)&S,    g_S);
    cudaGetSymbolAddress((void**)&q,    g_q);
    cudaGetSymbolAddress((void**)&k,    g_k);
    cudaGetSymbolAddress((void**)&hid,  g_h);
    cudaGetSymbolAddress((void**)&attn, g_attn);
    cudaGetSymbolAddress((void**)&rowv, g_rowv);
    cudaGetSymbolAddress((void**)&rowp, g_rowp);
    cudaGetSymbolAddress((void**)&pos,  g_pos);
    cudaGetSymbolAddress((void**)&cnt,  g_cnt);

    // 0) fp16 conversions: A hi-only (vectorized); B via coalesced transpose
    convA_kernel<<<(M_ * KP_ / 4 + 255) / 256, 256>>>(fuse, Ahi);
    transB_kernel<<<dim3(KP_ / 32, (D_ + 31) / 32, 3), 256>>>(Wq, Wk, Wgc, Bh);

    // 1) fused HMMA GEMM (hi term only, 2 CTA/SM) -> q, k, hidden (stride 792)
    cudaFuncSetAttribute(gemm_hmma_kernel, cudaFuncAttributeMaxDynamicSharedMemorySize, GEMM_SMEM);
    gemm_hmma_kernel<<<dim3(NPAD_ / 128, M_ / 128), 256, GEMM_SMEM>>>(
        Ahi, Bh, bq, bk, q, k, hid);

    // 2) pack q (hi/lo) and k (hi) head-padded fp16 (vectorized)
    pack_qk_kernel<<<(BHN * 16 + 255) / 256, 256>>>(q, k, Qhi, Qlo, Khi);

    // 3) HMMA score GEMM (k-major, shared Khi, 2 CTA/SM) -> S[B,H,N,N] fp16
    cudaFuncSetAttribute(score_hmma_kernel, cudaFuncAttributeMaxDynamicSharedMemorySize, SGEMM_SMEM);
    score_hmma_kernel<<<dim3(N_ / 128, N_ / 128, B_ * H_), 256, SGEMM_SMEM>>>(
        Qhi, Qlo, Khi, S);

    // 4) softmax + head-sum -> attn + per-row top-2 candidates
    softmax_kernel<<<M_, 256>>>(S, attn, rowv, rowp);

    // 5) per-batch top-2 threshold from candidates (no full-matrix scan)
    top2_kernel<<<B_, 256>>>(rowv, rowp, pos, cnt);

    // 6) sparse adjacency apply + graph-conv epilogue
    out_kernel<<<dim3(N_, B_), 256>>>(attn, hid, bgc, pos, cnt, out);
}

// round 17
// speedup vs baseline: 1.3087x; 1.0028x over previous
#include <cuda_runtime.h>
#include <cuda_fp16.h>
#include <cfloat>
#include <cstdint>

// Problem constants
#define B_   32
#define N_   512
#define D_   791
#define H_   7
#define DK_  113
#define M_   (B_ * N_)     // 16384
#define MAXP 64
#define QP_  792            // padded row stride for q/k/hid (fp32), 8B-aligned pairs

// main HMMA GEMM: CTA 128x128, warp tile 32x64, 8 warps, 3-stage, 2 CTA/SM
#define KP_     832          // padded K (13 * 64)
#define NCH     13           // single hi term, 13 chunks of K=64
#define NPAD_   2432         // fused N = 3*791 = 2373 padded to 19*128
#define STAGE_B 32768
#define GEMM_SMEM (3 * STAGE_B + 256)
#define BHN (B_ * H_ * N_)   // 114688 packed rows

// score GEMM: CTA 128x128, 2 k-half stages of {Qhi,Qlo,Khi} (48KB each)
#define SKP   128
#define SSTAGE_B 49152
#define SGEMM_SMEM (2 * SSTAGE_B + 256)
#define EPI_STRIDE 272       // fp16 staging row stride (bytes): 16B-aligned, conflict-free

// ---------------- scratch (device globals; no allocation allowed) -------------
__device__ __align__(256) __half g_Ahi[M_ * KP_];
__device__ __align__(256) __half g_Bh [NPAD_ * KP_];   // zero-init; transB fills n<791
__device__ __align__(256) __half g_Qhi[(size_t)BHN * SKP];
__device__ __align__(256) __half g_Qlo[(size_t)BHN * SKP];
__device__ __align__(256) __half g_Khi[(size_t)BHN * SKP];
__device__ __align__(256) __half g_S[(size_t)B_ * H_ * N_ * N_];
__device__ __align__(256) float g_q[(size_t)M_ * QP_];
__device__ __align__(256) float g_k[(size_t)M_ * QP_];
__device__ __align__(256) float g_h[(size_t)M_ * QP_];
__device__ float g_rowv[M_ * 2];     // per-row top-2 values
__device__ int   g_rowp[M_ * 2];     // per-row top-2 positions
__device__ float g_diag[M_];         // attn[n][n]
__device__ float g_mx[BHN];          // per-(b,h,n) softmax max
__device__ float g_wi[BHN];          // per-(b,h,n) softmax 1/sum
__device__ int   g_pos[B_ * MAXP * 2];
__device__ int   g_cnt[B_];

// ---------------- PTX helpers --------------------------------------------------
__device__ __forceinline__ uint32_t smem_u32(const void* p) {
    uint32_t a;
    asm("{ .reg .u64 t; cvta.to.shared.u64 t, %1; cvt.u32.u64 %0, t; }" : "=r"(a) : "l"(p));
    return a;
}
__device__ __forceinline__ void ldm4(uint32_t& r0, uint32_t& r1, uint32_t& r2,
                                     uint32_t& r3, uint32_t a) {
    asm volatile("ldmatrix.sync.aligned.m8n8.x4.shared.b16 {%0,%1,%2,%3}, [%4];"
                 : "=r"(r0), "=r"(r1), "=r"(r2), "=r"(r3) : "r"(a));
}
__device__ __forceinline__ void mma16816(float* d, const uint32_t* a, const uint32_t* b) {
    asm volatile(
        "mma.sync.aligned.m16n8k16.row.col.f32.f16.f16.f32 "
        "{%0,%1,%2,%3}, {%4,%5,%6,%7}, {%8,%9}, {%0,%1,%2,%3};"
        : "+f"(d[0]), "+f"(d[1]), "+f"(d[2]), "+f"(d[3])
        : "r"(a[0]), "r"(a[1]), "r"(a[2]), "r"(a[3]), "r"(b[0]), "r"(b[1]));
}
__device__ __forceinline__ void cpa16(uint32_t dst, const void* src) {
    asm volatile("cp.async.cg.shared.global [%0], [%1], 16;" :: "r"(dst), "l"(src));
}

// ---------------- conversions ----------------------------------------------------
__global__ __launch_bounds__(256) void convA_kernel(
    const float* __restrict__ fuse, __half* __restrict__ Ahi)
{
    int idx = blockIdx.x * 256 + threadIdx.x;      // over M_*KP_/4
    if (idx >= M_ * KP_ / 4) return;
    int m = idx / (KP_ / 4);
    int k = (idx - m * (KP_ / 4)) * 4;
    const float* src = fuse + (size_t)m * D_ + k;
    float x0 = (k     < D_) ? __ldg(src)     : 0.f;
    float x1 = (k + 1 < D_) ? __ldg(src + 1) : 0.f;
    float x2 = (k + 2 < D_) ? __ldg(src + 2) : 0.f;
    float x3 = (k + 3 < D_) ? __ldg(src + 3) : 0.f;
    __half2 h01 = __floats2half2_rn(x0, x1);
    __half2 h23 = __floats2half2_rn(x2, x3);
    uint2 o;
    o.x = *reinterpret_cast<uint32_t*>(&h01);
    o.y = *reinterpret_cast<uint32_t*>(&h23);
    *reinterpret_cast<uint2*>(Ahi + (size_t)idx * 4) = o;
}

// Coalesced transpose: Bh[z*791 + n][k] = W_z[k][n], 32x32 smem tiles.
__global__ __launch_bounds__(256) void transB_kernel(
    const float* __restrict__ Wq, const float* __restrict__ Wk,
    const float* __restrict__ Wgc, __half* __restrict__ Bh)
{
    __shared__ __half tile[32][33];
    const int z = blockIdx.z;
    const float* W = (z == 0) ? Wq : (z == 1) ? Wk : Wgc;
    const int k0 = blockIdx.x * 32;
    const int n0 = blockIdx.y * 32;
    const int tx = threadIdx.x & 31, ty = threadIdx.x >> 5;

    #pragma unroll
    for (int rr = 0; rr < 4; rr++) {
        int k = k0 + ty + rr * 8;
        int n = n0 + tx;
        float v = (k < D_ && n < D_) ? W[(size_t)k * D_ + n] : 0.f;
        tile[ty + rr * 8][tx] = __float2half_rn(v);
    }
    __syncthreads();
    #pragma unroll
    for (int rr = 0; rr < 4; rr++) {
        int n = n0 + ty + rr * 8;
        int k = k0 + tx;
        if (n < D_ && k < KP_)
            Bh[(size_t)(z * D_ + n) * KP_ + k] = tile[tx][ty + rr * 8];
    }
}

// ---------------- HMMA fused GEMM (single hi term, 128x128, 3-stage) -------------
__device__ __forceinline__ void issue_chunk(
    int cc, int tid, int m0, int nt0, uint32_t sb,
    const __half* __restrict__ Ahi, const __half* __restrict__ Bh)
{
    const int kk0 = cc * 64;
    const uint32_t st = sb + (cc % 3) * STAGE_B;
    #pragma unroll
    for (int it = 0; it < 4; it++) {               // A: 1024 x 16B
        int i = tid + it * 256;
        int r = i >> 3, u = i & 7;
        const __half* src = Ahi + (size_t)(m0 + r) * KP_ + kk0 + u * 8;
        cpa16(st + r * 128 + (((u ^ (r & 7))) << 4), src);
    }
    #pragma unroll
    for (int it = 0; it < 4; it++) {               // B: 1024 x 16B
        int i = tid + it * 256;
        int r = i >> 3, u = i & 7;
        const __half* src = Bh + (size_t)(nt0 + r) * KP_ + kk0 + u * 8;
        cpa16(st + 16384 + r * 128 + (((u ^ (r & 7))) << 4), src);
    }
    asm volatile("cp.async.commit_group;" ::: "memory");
}

__global__ __launch_bounds__(256, 2) void gemm_hmma_kernel(
    const __half* __restrict__ Ahi, const __half* __restrict__ Bh,
    const float* __restrict__ bq, const float* __restrict__ bk,
    float* __restrict__ q, float* __restrict__ kk, float* __restrict__ hid)
{
    extern __shared__ char smc[];
    const uint32_t sb = (smem_u32(smc) + 127) & ~127u;
    const int tid = threadIdx.x;
    const int wid = tid >> 5, lane = tid & 31;
    const int m0 = blockIdx.y * 128;
    const int nt0 = blockIdx.x * 128;

    float acc[2][8][4];
    #pragma unroll
    for (int t = 0; t < 2; t++)
        #pragma unroll
        for (int j = 0; j < 8; j++)
            #pragma unroll
            for (int e = 0; e < 4; e++) acc[t][j][e] = 0.f;

    issue_chunk(0, tid, m0, nt0, sb, Ahi, Bh);
    issue_chunk(1, tid, m0, nt0, sb, Ahi, Bh);

    const int warp_m = wid & 3, warp_n = wid >> 2;
    const int rowinA = (lane & 7) + ((lane >> 3) & 1) * 8;
    const int hbA    = lane >> 4;
    const int rowinB = (lane & 7) + ((lane >> 4) & 1) * 8;
    const int hbB    = (lane >> 3) & 1;

    for (int cc = 0; cc < NCH; cc++) {
        if (cc == NCH - 1) asm volatile("cp.async.wait_group 0;" ::: "memory");
        else               asm volatile("cp.async.wait_group 1;" ::: "memory");
        __syncthreads();
        if (cc + 2 < NCH) issue_chunk(cc + 2, tid, m0, nt0, sb, Ahi, Bh);

        const uint32_t st = sb + (cc % 3) * STAGE_B;
        #pragma unroll
        for (int s = 0; s < 4; s++) {
            uint32_t a[2][4], b[8][2];
            #pragma unroll
            for (int t = 0; t < 2; t++) {
                int r = warp_m * 32 + t * 16 + rowinA;
                uint32_t ad = st + r * 128 + ((((s << 1) | hbA) ^ (r & 7)) << 4);
                ldm4(a[t][0], a[t][1], a[t][2], a[t][3], ad);
            }
            #pragma unroll
            for (int jj = 0; jj < 4; jj++) {
                int r = warp_n * 64 + jj * 16 + rowinB;
                uint32_t ad = st + 16384 + r * 128 + ((((s << 1) | hbB) ^ (r & 7)) << 4);
                ldm4(b[2 * jj][0], b[2 * jj][1], b[2 * jj + 1][0], b[2 * jj + 1][1], ad);
            }
            #pragma unroll
            for (int t = 0; t < 2; t++)
                #pragma unroll
                for (int j = 0; j < 8; j++)
                    mma16816(acc[t][j], a[t], b[j]);
        }
    }

    // epilogue: demux to q | k | hid with bias. Row stride QP_=792; k at +1 base.
    #pragma unroll
    for (int t = 0; t < 2; t++) {
        const int row0 = m0 + warp_m * 32 + t * 16 + (lane >> 2);
        #pragma unroll
        for (int j = 0; j < 8; j++) {
            const int col = nt0 + warp_n * 64 + j * 8 + (lane & 3) * 2;
            #pragma unroll
            for (int half = 0; half < 2; half++) {
                const int row = row0 + half * 8;
                const float v0 = acc[t][j][half * 2];
                const float v1 = acc[t][j][half * 2 + 1];
                if (col + 1 < D_) {
                    float2 o = make_float2(v0 + __ldg(&bq[col]),
                                           v1 + __ldg(&bq[col + 1]));
                    *reinterpret_cast<float2*>(&q[(size_t)row * QP_ + col]) = o;
                } else if (col >= D_ && col + 1 < 2 * D_) {
                    float2 o = make_float2(v0 + __ldg(&bk[col - D_]),
                                           v1 + __ldg(&bk[col - D_ + 1]));
                    *reinterpret_cast<float2*>(&kk[(size_t)row * QP_ + 1 + (col - D_)]) = o;
                } else if (col >= 2 * D_ && col + 1 < 3 * D_) {
                    *reinterpret_cast<float2*>(&hid[(size_t)row * QP_ + (col - 2 * D_)]) =
                        make_float2(v0, v1);
                } else {
                    #pragma unroll
                    for (int e = 0; e < 2; e++) {
                        const int c = col + e;
                        const float v = e ? v1 : v0;
                        if (c < D_)
                            q[(size_t)row * QP_ + c] = v + __ldg(&bq[c]);
                        else if (c < 2 * D_)
                            kk[(size_t)row * QP_ + 1 + (c - D_)] = v + __ldg(&bk[c - D_]);
                        else if (c < 3 * D_)
                            hid[(size_t)row * QP_ + (c - 2 * D_)] = v;
                    }
                }
            }
        }
    }
}

// ---------------- pack q/k: q -> hi/lo, k -> hi only (8 elems/thread) -----------
__global__ __launch_bounds__(256) void pack_qk_kernel(
    const float* __restrict__ q, const float* __restrict__ k,
    __half* __restrict__ Qhi, __half* __restrict__ Qlo, __half* __restrict__ Khi)
{
    int idx = blockIdx.x * 256 + threadIdx.x;      // over BHN*16 (8 elems each)
    if (idx >= BHN * 16) return;
    const int dk0 = (idx & 15) * 8;
    const int rest = idx >> 4;
    const int n = rest & (N_ - 1);
    const int bh = rest >> 9;
    const int h = bh % H_, b = bh / H_;
    const size_t off = ((size_t)(b * N_ + n)) * QP_ + h * DK_;

    uint32_t qh[4], ql[4], kh[4];
    #pragma unroll
    for (int p = 0; p < 4; p++) {
        float qv0 = 0.f, qv1 = 0.f, kv0 = 0.f, kv1 = 0.f;
        int d0 = dk0 + p * 2, d1 = d0 + 1;
        if (d0 < DK_) { qv0 = __ldg(&q[off + d0]); kv0 = __ldg(&k[off + 1 + d0]); }
        if (d1 < DK_) { qv1 = __ldg(&q[off + d1]); kv1 = __ldg(&k[off + 1 + d1]); }
        __half2 qh2 = __floats2half2_rn(qv0, qv1);
        __half2 kh2 = __floats2half2_rn(kv0, kv1);
        __half2 ql2 = __floats2half2_rn(qv0 - __half2float(__low2half(qh2)),
                                        qv1 - __half2float(__high2half(qh2)));
        qh[p] = *reinterpret_cast<uint32_t*>(&qh2);
        ql[p] = *reinterpret_cast<uint32_t*>(&ql2);
        kh[p] = *reinterpret_cast<uint32_t*>(&kh2);
    }
    const size_t dst = (size_t)idx * 8;
    *reinterpret_cast<uint4*>(Qhi + dst) = make_uint4(qh[0], qh[1], qh[2], qh[3]);
    *reinterpret_cast<uint4*>(Qlo + dst) = make_uint4(ql[0], ql[1], ql[2], ql[3]);
    *reinterpret_cast<uint4*>(Khi + dst) = make_uint4(kh[0], kh[1], kh[2], kh[3]);
}

// ---------------- HMMA score GEMM (k-major: shared Khi tile per k-half) ----------
__device__ __forceinline__ void issue_s(
    int cc, int tid, int m0, int nt0, int bh, uint32_t sb,
    const __half* __restrict__ Qhi, const __half* __restrict__ Qlo,
    const __half* __restrict__ Khi)
{
    const int kk0 = cc * 64;
    const size_t base = (size_t)bh * N_ * SKP;
    const uint32_t st = sb + cc * SSTAGE_B;
    #pragma unroll
    for (int it = 0; it < 4; it++) {               // Qhi: 1024 x 16B
        int i = tid + it * 256;
        int r = i >> 3, u = i & 7;
        const __half* src = Qhi + base + (size_t)(m0 + r) * SKP + kk0 + u * 8;
        cpa16(st + r * 128 + (((u ^ (r & 7))) << 4), src);
    }
    #pragma unroll
    for (int it = 0; it < 4; it++) {               // Qlo: 1024 x 16B
        int i = tid + it * 256;
        int r = i >> 3, u = i & 7;
        const __half* src = Qlo + base + (size_t)(m0 + r) * SKP + kk0 + u * 8;
        cpa16(st + 16384 + r * 128 + (((u ^ (r & 7))) << 4), src);
    }
    #pragma unroll
    for (int it = 0; it < 4; it++) {               // Khi: 1024 x 16B
        int i = tid + it * 256;
        int r = i >> 3, u = i & 7;
        const __half* src = Khi + base + (size_t)(nt0 + r) * SKP + kk0 + u * 8;
        cpa16(st + 32768 + r * 128 + (((u ^ (r & 7))) << 4), src);
    }
    asm volatile("cp.async.commit_group;" ::: "memory");
}

__global__ __launch_bounds__(256, 2) void score_hmma_kernel(
    const __half* __restrict__ Qhi, const __half* __restrict__ Qlo,
    const __half* __restrict__ Khi, __half* __restrict__ S)
{
    extern __shared__ char smc[];
    char* smb = (char*)(((uintptr_t)smc + 127) & ~(uintptr_t)127);
    const uint32_t sb = smem_u32(smb);
    const int tid = threadIdx.x;
    const int wid = tid >> 5, lane = tid & 31;
    const int m0 = blockIdx.y * 128;
    const int nt0 = blockIdx.x * 128;
    const int bh = blockIdx.z;

    float acc[2][8][4];
    #pragma unroll
    for (int t = 0; t < 2; t++)
        #pragma unroll
        for (int j = 0; j < 8; j++)
            #pragma unroll
            for (int e = 0; e < 4; e++) acc[t][j][e] = 0.f;

    issue_s(0, tid, m0, nt0, bh, sb, Qhi, Qlo, Khi);
    issue_s(1, tid, m0, nt0, bh, sb, Qhi, Qlo, Khi);

    const int warp_m = wid & 3, warp_n = wid >> 2;
    const int rowinA = (lane & 7) + ((lane >> 3) & 1) * 8;
    const int hbA    = lane >> 4;
    const int rowinB = (lane & 7) + ((lane >> 4) & 1) * 8;
    const int hbB    = (lane >> 3) & 1;

    #pragma unroll
    for (int cc = 0; cc < 2; cc++) {
        if (cc == 0) asm volatile("cp.async.wait_group 1;" ::: "memory");
        else         asm volatile("cp.async.wait_group 0;" ::: "memory");
        __syncthreads();

        const uint32_t st = sb + cc * SSTAGE_B;
        #pragma unroll
        for (int s = 0; s < 4; s++) {
            uint32_t ah[2][4], al[2][4], b[8][2];
            #pragma unroll
            for (int t = 0; t < 2; t++) {
                int r = warp_m * 32 + t * 16 + rowinA;
                uint32_t byteoff = r * 128 + ((((s << 1) | hbA) ^ (r & 7)) << 4);
                ldm4(ah[t][0], ah[t][1], ah[t][2], ah[t][3], st + byteoff);
                ldm4(al[t][0], al[t][1], al[t][2], al[t][3], st + 16384 + byteoff);
            }
            #pragma unroll
            for (int jj = 0; jj < 4; jj++) {
                int r = warp_n * 64 + jj * 16 + rowinB;
                uint32_t ad = st + 32768 + r * 128 + ((((s << 1) | hbB) ^ (r & 7)) << 4);
                ldm4(b[2 * jj][0], b[2 * jj][1], b[2 * jj + 1][0], b[2 * jj + 1][1], ad);
            }
            #pragma unroll
            for (int t = 0; t < 2; t++)
                #pragma unroll
                for (int j = 0; j < 8; j++) {
                    mma16816(acc[t][j], ah[t], b[j]);
                    mma16816(acc[t][j], al[t], b[j]);
                }
        }
        __syncthreads();
    }

    // ---- fp16 epilogue: stage 128x128 half tile in smem, write coalesced ----
    const float scale = rsqrtf((float)DK_);
    #pragma unroll
    for (int t = 0; t < 2; t++) {
        const int rl0 = warp_m * 32 + t * 16 + (lane >> 2);
        #pragma unroll
        for (int j = 0; j < 8; j++) {
            const int cl = warp_n * 64 + j * 8 + (lane & 3) * 2;
            #pragma unroll
            for (int half = 0; half < 2; half++) {
                const int rl = rl0 + half * 8;
                __half2 hv = __floats2half2_rn(acc[t][j][half * 2] * scale,
                                               acc[t][j][half * 2 + 1] * scale);
                *reinterpret_cast<uint32_t*>(smb + rl * EPI_STRIDE + cl * 2) =
                    *reinterpret_cast<uint32_t*>(&hv);
            }
        }
    }
    __syncthreads();

    {
        const int row = tid >> 1, seg = tid & 1;
        const char* src = smb + row * EPI_STRIDE + seg * 128;
        __half* dst = S + (size_t)bh * N_ * N_ + (size_t)(m0 + row) * N_ + nt0 + seg * 64;
        #pragma unroll
        for (int u = 0; u < 8; u++)
            *reinterpret_cast<uint4*>(dst + u * 8) =
                *reinterpret_cast<const uint4*>(src + u * 16);
    }
}

// ---------------- softmax + head-sum -> row top-2 + diag + mx/winv ---------------
__global__ __launch_bounds__(256) void softmax_kernel(
    const __half* __restrict__ S,
    float* __restrict__ rowv, int* __restrict__ rowp,
    float* __restrict__ diag, float* __restrict__ mxo, float* __restrict__ wio)
{
    __shared__ float e[H_][N_];
    __shared__ float winv[H_];
    __shared__ float wv1[8], wv2[8];
    __shared__ int   wp1[8], wp2[8];

    const int tid = threadIdx.x;
    const int wid = tid >> 5, lane = tid & 31;
    const int ng = blockIdx.x;
    const int b = ng >> 9, n = ng & (N_ - 1);

    if (wid < H_) {
        const __half2* Sr2 = reinterpret_cast<const __half2*>(
            S + ((size_t)(b * H_ + wid) * N_ + n) * N_);
        float v[16];
        float mx = -FLT_MAX;
        #pragma unroll
        for (int it = 0; it < 8; it++) {
            float2 f = __half22float2(Sr2[lane + it * 32]);
            v[2 * it] = f.x;
            v[2 * it + 1] = f.y;
            mx = fmaxf(mx, fmaxf(f.x, f.y));
        }
        #pragma unroll
        for (int o = 16; o > 0; o >>= 1) mx = fmaxf(mx, __shfl_xor_sync(0xFFFFFFFFu, mx, o));
        float sum = 0.f;
        #pragma unroll
        for (int it = 0; it < 8; it++) {
            float e0 = __expf(v[2 * it] - mx);
            float e1 = __expf(v[2 * it + 1] - mx);
            e[wid][(lane + it * 32) * 2]     = e0;
            e[wid][(lane + it * 32) * 2 + 1] = e1;
            sum += e0 + e1;
        }
        #pragma unroll
        for (int o = 16; o > 0; o >>= 1) sum += __shfl_xor_sync(0xFFFFFFFFu, sum, o);
        if (lane == 0) {
            float wi = __frcp_rn(sum);
            winv[wid] = wi;
            mxo[(b * H_ + wid) * N_ + n] = mx;
            wio[(b * H_ + wid) * N_ + n] = wi;
        }
    }
    __syncthreads();

    // head-sum + per-thread top-2 (attn matrix is never materialized)
    float tv1 = -FLT_MAX, tv2 = -FLT_MAX;
    int   tp1 = 0, tp2 = 0;
    #pragma unroll
    for (int it = 0; it < 2; it++) {
        int m = tid + it * 256;
        float a = 0.f;
        #pragma unroll
        for (int h = 0; h < H_; h++) a += e[h][m] * winv[h];
        if (m == n) diag[ng] = a;
        if (a > tv1) { tv2 = tv1; tp2 = tp1; tv1 = a; tp1 = m; }
        else if (a > tv2) { tv2 = a; tp2 = m; }
    }
    // warp top-2 merge
    #pragma unroll
    for (int o = 16; o > 0; o >>= 1) {
        float ov1 = __shfl_xor_sync(0xFFFFFFFFu, tv1, o);
        float ov2 = __shfl_xor_sync(0xFFFFFFFFu, tv2, o);
        int   op1 = __shfl_xor_sync(0xFFFFFFFFu, tp1, o);
        int   op2 = __shfl_xor_sync(0xFFFFFFFFu, tp2, o);
        if (ov1 > tv1) {
            if (tv1 >= ov2) { tv2 = tv1; tp2 = tp1; }
            else            { tv2 = ov2; tp2 = op2; }
            tv1 = ov1; tp1 = op1;
        } else if (ov1 > tv2) {
            tv2 = ov1; tp2 = op1;
        }
    }
    if (lane == 0) { wv1[wid] = tv1; wv2[wid] = tv2; wp1[wid] = tp1; wp2[wid] = tp2; }
    __syncthreads();
    if (tid == 0) {
        float v1 = wv1[0], v2 = wv2[0];
        int   p1 = wp1[0], p2 = wp2[0];
        #pragma unroll
        for (int w = 1; w < 8; w++) {
            float a1 = wv1[w], a2 = wv2[w];
            int   b1 = wp1[w], b2 = wp2[w];
            if (a1 > v1) {
                if (v1 >= a2) { v2 = v1; p2 = p1; }
                else          { v2 = a2; p2 = b2; }
                v1 = a1; p1 = b1;
            } else if (a1 > v2) {
                v2 = a1; p2 = b1;
            }
        }
        rowv[ng * 2]     = v1;
        rowv[ng * 2 + 1] = v2;
        rowp[ng * 2]     = p1;
        rowp[ng * 2 + 1] = p2;
    }
}

// ---------------- per-batch top-2 from row candidates ---------------------------
__global__ __launch_bounds__(256) void top2_kernel(
    const float* __restrict__ rowv, const int* __restrict__ rowp,
    int* __restrict__ pos, int* __restrict__ cnt)
{
    __shared__ float v1s[256], v2s[256];
    __shared__ float s_kth;
    __shared__ int   s_cnt;

    const int b = blockIdx.x;
    const int tid = threadIdx.x;
    const float* V = rowv + b * N_ * 2;
    const int*   P = rowp + b * N_ * 2;

    float v1 = -FLT_MAX, v2 = -FLT_MAX;
    for (int i = tid; i < 2 * N_; i += 256) {
        float v = V[i];
        if (v > v1) { v2 = v1; v1 = v; }
        else if (v > v2) v2 = v;
    }
    v1s[tid] = v1; v2s[tid] = v2;
    __syncthreads();
    if (tid == 0) {
        float t1 = -FLT_MAX, t2 = -FLT_MAX;
        for (int i = 0; i < 256; i++) {
            float a = v1s[i], c = v2s[i];
            if (a > t1) { t2 = t1; t1 = a; } else if (a > t2) t2 = a;
            if (c > t1) { t2 = t1; t1 = c; } else if (c > t2) t2 = c;
        }
        s_kth = t2;
        s_cnt = 0;
    }
    __syncthreads();
    const float kth = s_kth;
    const int base = b * MAXP * 2;
    for (int i = tid; i < 2 * N_; i += 256) {
        if (V[i] >= kth) {
            int idx = atomicAdd(&s_cnt, 1);
            if (idx < MAXP) {
                pos[base + idx * 2]     = i >> 1;
                pos[base + idx * 2 + 1] = P[i];
            }
        }
    }
    __syncthreads();
    if (tid == 0) {
        int c = s_cnt < MAXP ? s_cnt : MAXP;
        for (int a2 = 1; a2 < c; a2++) {
            int ki = pos[base + a2 * 2], kj = pos[base + a2 * 2 + 1];
            int key = ki * N_ + kj;
            int p = a2 - 1;
            while (p >= 0) {
                int pi = pos[base + p * 2], pj = pos[base + p * 2 + 1];
                if (pi * N_ + pj <= key) break;
                pos[base + (p + 1) * 2] = pi;
                pos[base + (p + 1) * 2 + 1] = pj;
                p--;
            }
            pos[base + (p + 1) * 2] = ki;
            pos[base + (p + 1) * 2 + 1] = kj;
        }
        cnt[b] = c;
    }
}

// ---------------- sparse adjacency apply + GC epilogue --------------------------
// attn is never materialized: sparse weights recomputed from S + mx/winv
// (bit-identical: same __expf inputs as softmax used).
__device__ __forceinline__ float attn_val(
    const __half* __restrict__ S, const float* __restrict__ mx,
    const float* __restrict__ wi, int b, int n, int col)
{
    float a = 0.f;
    #pragma unroll
    for (int h = 0; h < H_; h++) {
        const int bhn = (b * H_ + h) * N_ + n;
        float s = __half2float(S[((size_t)(b * H_ + h) * N_ + n) * N_ + col]);
        a += __expf(s - mx[bhn]) * wi[bhn];
    }
    return a;
}

__global__ __launch_bounds__(256) void out_kernel(
    const __half* __restrict__ S, const float* __restrict__ mx,
    const float* __restrict__ wi, const float* __restrict__ diag,
    const float* __restrict__ hidden, const float* __restrict__ bgc,
    const int* __restrict__ pos, const int* __restrict__ cnt,
    float* __restrict__ out)
{
    const int b = blockIdx.y;
    const int n = blockIdx.x;
    const int tid = threadIdx.x;

    __shared__ int   s_nc;
    __shared__ int   s_cols[2 * MAXP];
    __shared__ float s_w[2 * MAXP];
    __shared__ float s_wd, s_inv;

    if (tid == 0) {
        const int base = b * MAXP * 2;
        int c = cnt[b];
        int nc = 0;
        float wd = diag[b * N_ + n];
        float sum = wd;
        for (int e = 0; e < c; e++) {
            int i = pos[base + e * 2], j = pos[base + e * 2 + 1];
            if (i == n && j != n) {
                float w = attn_val(S, mx, wi, b, n, j);
                s_cols[nc] = j; s_w[nc] = w; sum += w; nc++;
            }
            if (j == n && i != n) {
                float w = attn_val(S, mx, wi, b, n, i);
                s_cols[nc] = i; s_w[nc] = w; sum += w; nc++;
            }
        }
        s_nc = nc; s_wd = wd; s_inv = 1.f / (sum + 1.f);
    }
    __syncthreads();

    const int nc = s_nc;
    const float wd = s_wd, inv = s_inv;
    const float* hn = hidden + ((size_t)b * N_ + n) * QP_;
    float* on = out + ((size_t)b * N_ + n) * D_;

    for (int d = tid; d < D_; d += 256) {
        float v = wd * hn[d];
        for (int e = 0; e < nc; e++)
            v += s_w[e] * hidden[((size_t)b * N_ + s_cols[e]) * QP_ + d];
        v = v * inv + __ldg(&bgc[d]);
        on[d] = fmaxf(v, 0.f);
    }
}

// ---------------- launch ------------------------------------------------------
extern "C" void kernel_launch(void* const* d_in, const int* in_sizes, int n_in,
                              void* d_out, int out_size)
{
    const float* fuse = (const float*)d_in[0];
    const float* Wq   = (const float*)d_in[1];
    const float* bq   = (const float*)d_in[2];
    const float* Wk   = (const float*)d_in[3];
    const float* bk   = (const float*)d_in[4];
    const float* Wgc  = (const float*)d_in[5];
    const float* bgc  = (const float*)d_in[6];
    float* out = (float*)d_out;

    __half *Ahi, *Bh, *Qhi, *Qlo, *Khi, *S;
    float *q, *k, *hid, *rowv, *diag, *mx, *wi;
    int *rowp, *pos, *cnt;
    cudaGetSymbolAddress((void**)&Ahi,  g_Ahi);
    cudaGetSymbolAddress((void**)&Bh,   g_Bh);
    cudaGetSymbolAddress((void**)&Qhi,  g_Qhi);
    cudaGetSymbolAddress((void**)&Qlo,  g_Qlo);
    cudaGetSymbolAddress((void**)&Khi,  g_Khi);
    cudaGetSymbolAddress((void**)&S,    g_S);
    cudaGetSymbolAddress((void**)&q,    g_q);
    cudaGetSymbolAddress((void**)&k,    g_k);
    cudaGetSymbolAddress((void**)&hid,  g_h);
    cudaGetSymbolAddress((void**)&rowv, g_rowv);
    cudaGetSymbolAddress((void**)&rowp, g_rowp);
    cudaGetSymbolAddress((void**)&diag, g_diag);
    cudaGetSymbolAddress((void**)&mx,   g_mx);
    cudaGetSymbolAddress((void**)&wi,   g_wi);
    cudaGetSymbolAddress((void**)&pos,  g_pos);
    cudaGetSymbolAddress((void**)&cnt,  g_cnt);

    // 0) fp16 conversions
    convA_kernel<<<(M_ * KP_ / 4 + 255) / 256, 256>>>(fuse, Ahi);
    transB_kernel<<<dim3(KP_ / 32, (D_ + 31) / 32, 3), 256>>>(Wq, Wk, Wgc, Bh);

    // 1) fused HMMA GEMM -> q, k, hidden (stride 792)
    cudaFuncSetAttribute(gemm_hmma_kernel, cudaFuncAttributeMaxDynamicSharedMemorySize, GEMM_SMEM);
    gemm_hmma_kernel<<<dim3(NPAD_ / 128, M_ / 128), 256, GEMM_SMEM>>>(
        Ahi, Bh, bq, bk, q, k, hid);

    // 2) pack q (hi/lo) and k (hi)
    pack_qk_kernel<<<(BHN * 16 + 255) / 256, 256>>>(q, k, Qhi, Qlo, Khi);

    // 3) HMMA score GEMM -> S fp16
    cudaFuncSetAttribute(score_hmma_kernel, cudaFuncAttributeMaxDynamicSharedMemorySize, SGEMM_SMEM);
    score_hmma_kernel<<<dim3(N_ / 128, N_ / 128, B_ * H_), 256, SGEMM_SMEM>>>(
        Qhi, Qlo, Khi, S);

    // 4) softmax stats + row top-2 + diag (attn matrix never materialized)
    softmax_kernel<<<M_, 256>>>(S, rowv, rowp, diag, mx, wi);

    // 5) per-batch top-2 threshold from candidates
    top2_kernel<<<B_, 256>>>(rowv, rowp, pos, cnt);

    // 6) sparse adjacency apply (weights recomputed from S) + GC epilogue
    out_kernel<<<dim3(N_, B_), 256>>>(S, mx, wi, diag, hid, bgc, pos, cnt, out);
}